// round 1
// baseline (speedup 1.0000x reference)
#include <cuda_runtime.h>

#define NSEQ 1024
#define DIM  256
#define HEADS 8
#define EDIM 512
#define HD   64
#define PEC  32
#define BH   32           // B*HEADS
#define ROWS 4096         // B*N

// ---------------- scratch (device globals; no runtime allocation) ----------
__device__ float g_q[BH * NSEQ * HD];
__device__ float g_k[BH * NSEQ * HD];
__device__ float g_v[BH * NSEQ * HD];
__device__ float g_attn[(size_t)BH * NSEQ * NSEQ];   // 128 MB
__device__ float g_oh[BH * NSEQ * HD];
__device__ float g_pes[BH * NSEQ * PEC];
__device__ float g_merged[ROWS * EDIM];

// 4x4 microtile inner product over a 16-deep K slab
#define MICRO16()                                                              \
  _Pragma("unroll")                                                            \
  for (int kk = 0; kk < 16; kk++) {                                            \
    float4 a4 = *(const float4*)&As[kk * 68 + ty * 4];                         \
    float4 b4 = *(const float4*)&Bs[kk * 68 + tx * 4];                         \
    acc[0][0] += a4.x * b4.x; acc[0][1] += a4.x * b4.y;                        \
    acc[0][2] += a4.x * b4.z; acc[0][3] += a4.x * b4.w;                        \
    acc[1][0] += a4.y * b4.x; acc[1][1] += a4.y * b4.y;                        \
    acc[1][2] += a4.y * b4.z; acc[1][3] += a4.y * b4.w;                        \
    acc[2][0] += a4.z * b4.x; acc[2][1] += a4.z * b4.y;                        \
    acc[2][2] += a4.z * b4.z; acc[2][3] += a4.z * b4.w;                        \
    acc[3][0] += a4.w * b4.x; acc[3][1] += a4.w * b4.y;                        \
    acc[3][2] += a4.w * b4.z; acc[3][3] += a4.w * b4.w;                        \
  }

// ---------------- Kernel 1: fused QKV projection ---------------------------
// C(4096 x 1536) = x(4096 x 256) @ [Wq|Wk|Wv](256 x 1536), epilogue scatters
// into (bh, n, d) layout; q scaled by 1/8, v gets bias.
__global__ __launch_bounds__(256) void qkv_kernel(
    const float* __restrict__ x, const float* __restrict__ Wq,
    const float* __restrict__ Wk, const float* __restrict__ Wv,
    const float* __restrict__ bv) {
  __shared__ float As[16 * 68];
  __shared__ float Bs[16 * 68];
  int tid = threadIdx.x;
  int m0 = blockIdx.x * 64;
  int gc0 = blockIdx.y * 64;            // global col in [0,1536), 64-aligned
  int sel = gc0 / 512;                  // 0=q 1=k 2=v (tile never straddles)
  int e0 = gc0 % 512;                   // col within W
  int h = e0 / 64;                      // head (tile never straddles)
  const float* Bmat = (sel == 0) ? Wq : (sel == 1) ? Wk : Wv;
  int tx = tid & 15, ty = tid >> 4;
  int lm = tid >> 2, lk = (tid & 3) * 4;
  int bk = tid >> 4, bn = (tid & 15) * 4;
  float acc[4][4] = {};
  for (int kt = 0; kt < 256; kt += 16) {
    float4 av = *(const float4*)(x + (m0 + lm) * 256 + kt + lk);
    As[(lk + 0) * 68 + lm] = av.x; As[(lk + 1) * 68 + lm] = av.y;
    As[(lk + 2) * 68 + lm] = av.z; As[(lk + 3) * 68 + lm] = av.w;
    *(float4*)&Bs[bk * 68 + bn] =
        *(const float4*)(Bmat + (kt + bk) * 512 + e0 + bn);
    __syncthreads();
    MICRO16();
    __syncthreads();
  }
  float* dst = (sel == 0) ? g_q : (sel == 1) ? g_k : g_v;
#pragma unroll
  for (int i = 0; i < 4; i++) {
    int gr = m0 + ty * 4 + i;
    int b = gr >> 10, n = gr & 1023;
    size_t base = ((size_t)(b * 8 + h) * 1024 + n) * 64;
#pragma unroll
    for (int j = 0; j < 4; j++) {
      int c = tx * 4 + j;
      float v = acc[i][j];
      if (sel == 0) v *= 0.125f;            // head_dim^-0.5 folded into q
      if (sel == 2) v += bv[e0 + c];
      dst[base + c] = v;
    }
  }
}

// ---------------- Kernel 2: scores = q @ k^T (batched NT) ------------------
__global__ __launch_bounds__(256) void scores_kernel() {
  __shared__ float As[16 * 68];
  __shared__ float Bs[16 * 68];
  int tid = threadIdx.x;
  int bh = blockIdx.z;
  const float* Aq = g_q + (size_t)bh * NSEQ * HD;
  const float* Kk = g_k + (size_t)bh * NSEQ * HD;
  int m0 = blockIdx.x * 64, n0 = blockIdx.y * 64;
  int tx = tid & 15, ty = tid >> 4;
  int lm = tid >> 2, lk = (tid & 3) * 4;
  float acc[4][4] = {};
  for (int kt = 0; kt < 64; kt += 16) {
    float4 av = *(const float4*)(Aq + (m0 + lm) * 64 + kt + lk);
    As[(lk + 0) * 68 + lm] = av.x; As[(lk + 1) * 68 + lm] = av.y;
    As[(lk + 2) * 68 + lm] = av.z; As[(lk + 3) * 68 + lm] = av.w;
    float4 bvv = *(const float4*)(Kk + (n0 + lm) * 64 + kt + lk);
    Bs[(lk + 0) * 68 + lm] = bvv.x; Bs[(lk + 1) * 68 + lm] = bvv.y;
    Bs[(lk + 2) * 68 + lm] = bvv.z; Bs[(lk + 3) * 68 + lm] = bvv.w;
    __syncthreads();
    MICRO16();
    __syncthreads();
  }
  float* C = g_attn + (size_t)bh * NSEQ * NSEQ;
#pragma unroll
  for (int i = 0; i < 4; i++) {
    float4 o = make_float4(acc[i][0], acc[i][1], acc[i][2], acc[i][3]);
    *(float4*)&C[(size_t)(m0 + ty * 4 + i) * 1024 + n0 + tx * 4] = o;
  }
}

// ---------------- Kernel 3: row softmax in place ----------------------------
__global__ __launch_bounds__(256) void softmax_kernel() {
  int tid = threadIdx.x;
  int warp = tid >> 5, lane = tid & 31;
  size_t row = (size_t)blockIdx.x * 8 + warp;
  float* p = g_attn + row * 1024;
  float4 v[8];
  float mx = -1e30f;
#pragma unroll
  for (int m = 0; m < 8; m++) {
    v[m] = *(const float4*)(p + (m * 32 + lane) * 4);
    mx = fmaxf(mx, fmaxf(fmaxf(v[m].x, v[m].y), fmaxf(v[m].z, v[m].w)));
  }
#pragma unroll
  for (int o = 16; o; o >>= 1) mx = fmaxf(mx, __shfl_xor_sync(~0u, mx, o));
  float s = 0.f;
#pragma unroll
  for (int m = 0; m < 8; m++) {
    v[m].x = __expf(v[m].x - mx); v[m].y = __expf(v[m].y - mx);
    v[m].z = __expf(v[m].z - mx); v[m].w = __expf(v[m].w - mx);
    s += v[m].x + v[m].y + v[m].z + v[m].w;
  }
#pragma unroll
  for (int o = 16; o; o >>= 1) s += __shfl_xor_sync(~0u, s, o);
  float inv = 1.f / s;
#pragma unroll
  for (int m = 0; m < 8; m++) {
    v[m].x *= inv; v[m].y *= inv; v[m].z *= inv; v[m].w *= inv;
    *(float4*)(p + (m * 32 + lane) * 4) = v[m];
  }
}

// ---------------- Kernel 4: out_head = attn @ v (batched NN) ---------------
__global__ __launch_bounds__(256) void av_kernel() {
  __shared__ float As[16 * 68];
  __shared__ float Bs[16 * 68];
  int tid = threadIdx.x;
  int bh = blockIdx.z;
  const float* A = g_attn + (size_t)bh * NSEQ * NSEQ;
  const float* V = g_v + (size_t)bh * NSEQ * HD;
  int m0 = blockIdx.x * 64;
  int tx = tid & 15, ty = tid >> 4;
  int lm = tid >> 2, lk = (tid & 3) * 4;
  int bk = tid >> 4, bn = (tid & 15) * 4;
  float acc[4][4] = {};
  for (int kt = 0; kt < 1024; kt += 16) {
    float4 av = *(const float4*)(A + (size_t)(m0 + lm) * 1024 + kt + lk);
    As[(lk + 0) * 68 + lm] = av.x; As[(lk + 1) * 68 + lm] = av.y;
    As[(lk + 2) * 68 + lm] = av.z; As[(lk + 3) * 68 + lm] = av.w;
    *(float4*)&Bs[bk * 68 + bn] = *(const float4*)(V + (kt + bk) * 64 + bn);
    __syncthreads();
    MICRO16();
    __syncthreads();
  }
  float* C = g_oh + (size_t)bh * NSEQ * HD;
#pragma unroll
  for (int i = 0; i < 4; i++) {
    float4 o = make_float4(acc[i][0], acc[i][1], acc[i][2], acc[i][3]);
    *(float4*)&C[(m0 + ty * 4 + i) * 64 + tx * 4] = o;
  }
}

// ---------------- Kernel 5: pe_sum[bh,i,c] = sum_j attn[bh,i,j]*pe[i,j,c] --
// One CTA per i: pe[i] tile loaded once, reused by all 32 (b,h).
__global__ __launch_bounds__(256) void pes_kernel(const float* __restrict__ pe) {
  __shared__ float pe_s[128 * 32];   // 16 KB
  __shared__ float a_s[32 * 132];    // 16.9 KB
  int i = blockIdx.x;
  int tid = threadIdx.x;
  int bh = tid >> 3;                 // 0..31
  int c4 = tid & 7;                  // 4 channels each
  float4 acc = make_float4(0.f, 0.f, 0.f, 0.f);
  for (int jt = 0; jt < 1024; jt += 128) {
#pragma unroll
    for (int r = 0; r < 4; r++) {
      int idx4 = tid + r * 256;      // 0..1023
      int j = idx4 >> 3, cc = idx4 & 7;
      *(float4*)&pe_s[j * 32 + cc * 4] =
          *(const float4*)(pe + ((size_t)i * 1024 + jt + j) * 32 + cc * 4);
      int bb = idx4 >> 5, jj = idx4 & 31;
      *(float4*)&a_s[bb * 132 + jj * 4] =
          *(const float4*)(g_attn + (size_t)bb * NSEQ * NSEQ +
                           (size_t)i * 1024 + jt + jj * 4);
    }
    __syncthreads();
#pragma unroll 4
    for (int j = 0; j < 128; j++) {
      float a = a_s[bh * 132 + j];
      float4 pv = *(const float4*)&pe_s[j * 32 + c4 * 4];
      acc.x += a * pv.x; acc.y += a * pv.y;
      acc.z += a * pv.z; acc.w += a * pv.w;
    }
    __syncthreads();
  }
  *(float4*)&g_pes[((size_t)bh * 1024 + i) * 32 + c4 * 4] = acc;
}

// ---------------- Kernel 6: merged = out_head + pe_sum@Wpe + bpe -----------
__global__ __launch_bounds__(256) void merge_kernel(
    const float* __restrict__ Wpe, const float* __restrict__ bpe) {
  __shared__ float wpe_s[32 * 64];
  __shared__ float pes_s[32 * 32];
  __shared__ float bpe_s[64];
  int bh = blockIdx.x;
  int n0 = blockIdx.y * 32;
  int tid = threadIdx.x;
#pragma unroll
  for (int r = 0; r < 8; r++) wpe_s[tid + r * 256] = Wpe[tid + r * 256];
  if (tid < 64) bpe_s[tid] = bpe[tid];
  {
    int nl = tid >> 3, cc = tid & 7;
    *(float4*)&pes_s[nl * 32 + cc * 4] =
        *(const float4*)(g_pes + ((size_t)bh * 1024 + n0 + nl) * 32 + cc * 4);
  }
  __syncthreads();
  int nl = tid >> 3;
  int d0 = (tid & 7) * 8;
  int b = bh >> 3, h = bh & 7;
  const float* ohp = g_oh + ((size_t)bh * 1024 + n0 + nl) * 64 + d0;
  float o[8];
#pragma unroll
  for (int dd = 0; dd < 8; dd++) o[dd] = bpe_s[d0 + dd] + ohp[dd];
#pragma unroll 8
  for (int c = 0; c < 32; c++) {
    float pv = pes_s[nl * 32 + c];
#pragma unroll
    for (int dd = 0; dd < 8; dd++) o[dd] += pv * wpe_s[c * 64 + d0 + dd];
  }
  float* mp = g_merged + ((size_t)(b * 1024 + n0 + nl)) * 512 + h * 64 + d0;
#pragma unroll
  for (int dd = 0; dd < 8; dd++) mp[dd] = o[dd];
}

// ---------------- Kernel 7: out = merged @ Wproj ----------------------------
__global__ __launch_bounds__(256) void proj_kernel(
    const float* __restrict__ Wproj, float* __restrict__ out) {
  __shared__ float As[16 * 68];
  __shared__ float Bs[16 * 68];
  int tid = threadIdx.x;
  int m0 = blockIdx.x * 64, n0 = blockIdx.y * 64;
  int tx = tid & 15, ty = tid >> 4;
  int lm = tid >> 2, lk = (tid & 3) * 4;
  int bk = tid >> 4, bn = (tid & 15) * 4;
  float acc[4][4] = {};
  for (int kt = 0; kt < 512; kt += 16) {
    float4 av = *(const float4*)(g_merged + (size_t)(m0 + lm) * 512 + kt + lk);
    As[(lk + 0) * 68 + lm] = av.x; As[(lk + 1) * 68 + lm] = av.y;
    As[(lk + 2) * 68 + lm] = av.z; As[(lk + 3) * 68 + lm] = av.w;
    *(float4*)&Bs[bk * 68 + bn] =
        *(const float4*)(Wproj + (kt + bk) * 256 + n0 + bn);
    __syncthreads();
    MICRO16();
    __syncthreads();
  }
#pragma unroll
  for (int i = 0; i < 4; i++) {
    float4 o = make_float4(acc[i][0], acc[i][1], acc[i][2], acc[i][3]);
    *(float4*)&out[(size_t)(m0 + ty * 4 + i) * 256 + n0 + tx * 4] = o;
  }
}

// ---------------- launch -----------------------------------------------------
extern "C" void kernel_launch(void* const* d_in, const int* in_sizes, int n_in,
                              void* d_out, int out_size) {
  const float* x     = (const float*)d_in[0];
  const float* pe    = (const float*)d_in[1];
  const float* Wq    = (const float*)d_in[2];
  const float* Wk    = (const float*)d_in[3];
  const float* Wv    = (const float*)d_in[4];
  const float* bv    = (const float*)d_in[5];
  const float* Wpe   = (const float*)d_in[6];
  const float* bpe   = (const float*)d_in[7];
  const float* Wproj = (const float*)d_in[8];
  float* out = (float*)d_out;

  qkv_kernel<<<dim3(64, 24), 256>>>(x, Wq, Wk, Wv, bv);
  scores_kernel<<<dim3(16, 16, 32), 256>>>();
  softmax_kernel<<<4096, 256>>>();
  av_kernel<<<dim3(16, 1, 32), 256>>>();
  pes_kernel<<<1024, 256>>>(pe);
  merge_kernel<<<dim3(32, 32), 256>>>(Wpe, bpe);
  proj_kernel<<<dim3(64, 4), 256>>>(Wproj, out);
}

// round 3
// speedup vs baseline: 1.2466x; 1.2466x over previous
#include <cuda_runtime.h>
#include <cuda_bf16.h>
#include <cstdint>

#define NSEQ 1024
#define DIM  256
#define HEADS 8
#define EDIM 512
#define HD   64
#define PEC  32
#define BH   32           // B*HEADS
#define ROWS 4096         // B*N

// ---------------- scratch (device globals; no runtime allocation) ----------
__device__ __nv_bfloat16 g_qh[BH * NSEQ * HD];
__device__ __nv_bfloat16 g_ql[BH * NSEQ * HD];
__device__ __nv_bfloat16 g_kh[BH * NSEQ * HD];
__device__ __nv_bfloat16 g_kl[BH * NSEQ * HD];
__device__ __nv_bfloat16 g_vth[BH * HD * NSEQ];   // transposed: [bh][d][n]
__device__ __nv_bfloat16 g_vtl[BH * HD * NSEQ];
__device__ float g_attn[(size_t)BH * NSEQ * NSEQ];   // 128 MB
__device__ float g_oh[BH * NSEQ * HD];
__device__ float g_pes[BH * NSEQ * PEC];
__device__ float g_merged[ROWS * EDIM];

union B16x8 { __nv_bfloat16 h[8]; uint4 u; };

__device__ __forceinline__ void split2(float x, __nv_bfloat16& h, __nv_bfloat16& l) {
  h = __float2bfloat16_rn(x);
  l = __float2bfloat16_rn(x - __bfloat162float(h));
}

// m16n8k16 bf16 mma with fp32 accumulate (row.col)
__device__ __forceinline__ void mma16816(float* c, const uint32_t* a,
                                         const uint32_t* b) {
  asm volatile(
      "mma.sync.aligned.m16n8k16.row.col.f32.bf16.bf16.f32 "
      "{%0,%1,%2,%3}, {%4,%5,%6,%7}, {%8,%9}, {%0,%1,%2,%3};"
      : "+f"(c[0]), "+f"(c[1]), "+f"(c[2]), "+f"(c[3])
      : "r"(a[0]), "r"(a[1]), "r"(a[2]), "r"(a[3]), "r"(b[0]), "r"(b[1]));
}

#define LDSTRIDE 72   // bf16 units per SMEM row (64 data + 8 pad)

// 4x4 microtile inner product over a 16-deep K slab (fp32 GEMMs)
#define MICRO16()                                                              \
  _Pragma("unroll")                                                            \
  for (int kk = 0; kk < 16; kk++) {                                            \
    float4 a4 = *(const float4*)&As[kk * 68 + ty * 4];                         \
    float4 b4 = *(const float4*)&Bs[kk * 68 + tx * 4];                         \
    acc[0][0] += a4.x * b4.x; acc[0][1] += a4.x * b4.y;                        \
    acc[0][2] += a4.x * b4.z; acc[0][3] += a4.x * b4.w;                        \
    acc[1][0] += a4.y * b4.x; acc[1][1] += a4.y * b4.y;                        \
    acc[1][2] += a4.y * b4.z; acc[1][3] += a4.y * b4.w;                        \
    acc[2][0] += a4.z * b4.x; acc[2][1] += a4.z * b4.y;                        \
    acc[2][2] += a4.z * b4.z; acc[2][3] += a4.z * b4.w;                        \
    acc[3][0] += a4.w * b4.x; acc[3][1] += a4.w * b4.y;                        \
    acc[3][2] += a4.w * b4.z; acc[3][3] += a4.w * b4.w;                        \
  }

// ---------------- Kernel 1: fused QKV projection ---------------------------
__global__ __launch_bounds__(256) void qkv_kernel(
    const float* __restrict__ x, const float* __restrict__ Wq,
    const float* __restrict__ Wk, const float* __restrict__ Wv,
    const float* __restrict__ bv) {
  __shared__ float As[16 * 68];
  __shared__ float Bs[16 * 68];
  int tid = threadIdx.x;
  int m0 = blockIdx.x * 64;
  int gc0 = blockIdx.y * 64;
  int sel = gc0 / 512;
  int e0 = gc0 % 512;
  int h = e0 / 64;
  const float* Bmat = (sel == 0) ? Wq : (sel == 1) ? Wk : Wv;
  int tx = tid & 15, ty = tid >> 4;
  int lm = tid >> 2, lk = (tid & 3) * 4;
  int bk = tid >> 4, bn = (tid & 15) * 4;
  float acc[4][4] = {};
  for (int kt = 0; kt < 256; kt += 16) {
    float4 av = *(const float4*)(x + (m0 + lm) * 256 + kt + lk);
    As[(lk + 0) * 68 + lm] = av.x; As[(lk + 1) * 68 + lm] = av.y;
    As[(lk + 2) * 68 + lm] = av.z; As[(lk + 3) * 68 + lm] = av.w;
    *(float4*)&Bs[bk * 68 + bn] =
        *(const float4*)(Bmat + (kt + bk) * 512 + e0 + bn);
    __syncthreads();
    MICRO16();
    __syncthreads();
  }
#pragma unroll
  for (int i = 0; i < 4; i++) {
    int gr = m0 + ty * 4 + i;
    int b = gr >> 10, n = gr & 1023;
    int bh = b * 8 + h;
#pragma unroll
    for (int j = 0; j < 4; j++) {
      int c = tx * 4 + j;
      float v = acc[i][j];
      __nv_bfloat16 hi, lo;
      if (sel == 0) {
        v *= 0.125f;
        split2(v, hi, lo);
        size_t idx = ((size_t)bh * 1024 + n) * 64 + c;
        g_qh[idx] = hi; g_ql[idx] = lo;
      } else if (sel == 1) {
        split2(v, hi, lo);
        size_t idx = ((size_t)bh * 1024 + n) * 64 + c;
        g_kh[idx] = hi; g_kl[idx] = lo;
      } else {
        v += bv[e0 + c];
        split2(v, hi, lo);
        size_t idx = ((size_t)bh * 64 + c) * 1024 + n;   // transposed
        g_vth[idx] = hi; g_vtl[idx] = lo;
      }
    }
  }
}

// ---------------- Kernel 2: scores = q @ k^T via mma.sync (split bf16) -----
// CTA = 128 (i) x 128 (j), K = 64. grid (8, 8, 32). 8 warps in 2x4 grid.
#define S_SMEM_BYTES (4 * 128 * LDSTRIDE * 2)
__global__ __launch_bounds__(256) void scores_mma() {
  extern __shared__ __nv_bfloat16 sm[];
  __nv_bfloat16* QHs = sm;
  __nv_bfloat16* QLs = QHs + 128 * LDSTRIDE;
  __nv_bfloat16* KHs = QLs + 128 * LDSTRIDE;
  __nv_bfloat16* KLs = KHs + 128 * LDSTRIDE;

  int tid = threadIdx.x;
  int wid = tid >> 5, lane = tid & 31;
  int bh = blockIdx.z;
  int i0 = blockIdx.x * 128;
  int j0 = blockIdx.y * 128;

  const __nv_bfloat16* qh = g_qh + (size_t)bh * NSEQ * HD;
  const __nv_bfloat16* ql = g_ql + (size_t)bh * NSEQ * HD;
  const __nv_bfloat16* kh = g_kh + (size_t)bh * NSEQ * HD;
  const __nv_bfloat16* kl = g_kl + (size_t)bh * NSEQ * HD;
#pragma unroll
  for (int t = 0; t < 4; t++) {
    int idx = tid + 256 * t;          // 0..1023 covers 128 rows x 8 segs
    int r = idx >> 3, seg = idx & 7;
    int so = r * LDSTRIDE + seg * 8;
    *(uint4*)(QHs + so) = *(const uint4*)(qh + (i0 + r) * 64 + seg * 8);
    *(uint4*)(QLs + so) = *(const uint4*)(ql + (i0 + r) * 64 + seg * 8);
    *(uint4*)(KHs + so) = *(const uint4*)(kh + (j0 + r) * 64 + seg * 8);
    *(uint4*)(KLs + so) = *(const uint4*)(kl + (j0 + r) * 64 + seg * 8);
  }
  __syncthreads();

  int m_w = (wid & 1) * 64;           // 2 warps along m
  int n_w = (wid >> 1) * 32;          // 4 warps along n
  int r = lane >> 2, kq = (lane & 3) * 2;

  float c[4][4][4];
#pragma unroll
  for (int mt = 0; mt < 4; mt++)
#pragma unroll
    for (int nt = 0; nt < 4; nt++)
#pragma unroll
      for (int e = 0; e < 4; e++) c[mt][nt][e] = 0.f;

#pragma unroll
  for (int kb = 0; kb < 64; kb += 16) {
    uint32_t ah[4][4], al[4][4];
#pragma unroll
    for (int mt = 0; mt < 4; mt++) {
      int row = m_w + mt * 16 + r;
      const __nv_bfloat16* p = QHs + row * LDSTRIDE + kb + kq;
      ah[mt][0] = *(const uint32_t*)p;
      ah[mt][1] = *(const uint32_t*)(p + 8 * LDSTRIDE);
      ah[mt][2] = *(const uint32_t*)(p + 8);
      ah[mt][3] = *(const uint32_t*)(p + 8 * LDSTRIDE + 8);
      const __nv_bfloat16* q = QLs + row * LDSTRIDE + kb + kq;
      al[mt][0] = *(const uint32_t*)q;
      al[mt][1] = *(const uint32_t*)(q + 8 * LDSTRIDE);
      al[mt][2] = *(const uint32_t*)(q + 8);
      al[mt][3] = *(const uint32_t*)(q + 8 * LDSTRIDE + 8);
    }
    uint32_t bhf[4][2], blf[4][2];
#pragma unroll
    for (int nt = 0; nt < 4; nt++) {
      int nrow = n_w + nt * 8 + r;
      const __nv_bfloat16* p = KHs + nrow * LDSTRIDE + kb + kq;
      bhf[nt][0] = *(const uint32_t*)p;
      bhf[nt][1] = *(const uint32_t*)(p + 8);
      const __nv_bfloat16* q = KLs + nrow * LDSTRIDE + kb + kq;
      blf[nt][0] = *(const uint32_t*)q;
      blf[nt][1] = *(const uint32_t*)(q + 8);
    }
#pragma unroll
    for (int mt = 0; mt < 4; mt++)
#pragma unroll
      for (int nt = 0; nt < 4; nt++) {
        mma16816(c[mt][nt], ah[mt], bhf[nt]);
        mma16816(c[mt][nt], ah[mt], blf[nt]);
        mma16816(c[mt][nt], al[mt], bhf[nt]);
      }
  }

  float* C = g_attn + (size_t)bh * NSEQ * NSEQ;
#pragma unroll
  for (int mt = 0; mt < 4; mt++) {
#pragma unroll
    for (int nt = 0; nt < 4; nt++) {
      int row = i0 + m_w + mt * 16 + r;
      int col = j0 + n_w + nt * 8 + (lane & 3) * 2;
      float* dst = C + (size_t)row * 1024 + col;
      *(float2*)dst = make_float2(c[mt][nt][0], c[mt][nt][1]);
      *(float2*)(dst + 8 * 1024) = make_float2(c[mt][nt][2], c[mt][nt][3]);
    }
  }
}

// ---------------- Kernel 3: row softmax in place ----------------------------
__global__ __launch_bounds__(256) void softmax_kernel() {
  int tid = threadIdx.x;
  int warp = tid >> 5, lane = tid & 31;
  size_t row = (size_t)blockIdx.x * 8 + warp;
  float* p = g_attn + row * 1024;
  float4 v[8];
  float mx = -1e30f;
#pragma unroll
  for (int m = 0; m < 8; m++) {
    v[m] = *(const float4*)(p + (m * 32 + lane) * 4);
    mx = fmaxf(mx, fmaxf(fmaxf(v[m].x, v[m].y), fmaxf(v[m].z, v[m].w)));
  }
#pragma unroll
  for (int o = 16; o; o >>= 1) mx = fmaxf(mx, __shfl_xor_sync(~0u, mx, o));
  float s = 0.f;
#pragma unroll
  for (int m = 0; m < 8; m++) {
    v[m].x = __expf(v[m].x - mx); v[m].y = __expf(v[m].y - mx);
    v[m].z = __expf(v[m].z - mx); v[m].w = __expf(v[m].w - mx);
    s += v[m].x + v[m].y + v[m].z + v[m].w;
  }
#pragma unroll
  for (int o = 16; o; o >>= 1) s += __shfl_xor_sync(~0u, s, o);
  float inv = 1.f / s;
#pragma unroll
  for (int m = 0; m < 8; m++) {
    v[m].x *= inv; v[m].y *= inv; v[m].z *= inv; v[m].w *= inv;
    *(float4*)(p + (m * 32 + lane) * 4) = v[m];
  }
}

// ---------------- Kernel 4: out_head = attn @ v via mma.sync ----------------
// CTA = 128 (i) x 64 (d), K = 1024 in 16 chunks of 64. grid (8, 32).
#define AV_SMEM_BYTES ((2 * 128 + 2 * 64) * LDSTRIDE * 2)
__global__ __launch_bounds__(256) void av_mma() {
  extern __shared__ __nv_bfloat16 sm[];
  __nv_bfloat16* AHs = sm;
  __nv_bfloat16* ALs = AHs + 128 * LDSTRIDE;
  __nv_bfloat16* VHs = ALs + 128 * LDSTRIDE;
  __nv_bfloat16* VLs = VHs + 64 * LDSTRIDE;

  int tid = threadIdx.x;
  int wid = tid >> 5, lane = tid & 31;
  int bh = blockIdx.y;
  int i0 = blockIdx.x * 128;

  const float* A = g_attn + ((size_t)bh << 20);
  const __nv_bfloat16* vth = g_vth + (size_t)bh * HD * NSEQ;
  const __nv_bfloat16* vtl = g_vtl + (size_t)bh * HD * NSEQ;

  int m_w = (wid >> 1) * 32;          // 4 warps along m
  int n_w = (wid & 1) * 32;           // 2 warps along n
  int r = lane >> 2, kq = (lane & 3) * 2;

  float c[2][4][4];
#pragma unroll
  for (int mt = 0; mt < 2; mt++)
#pragma unroll
    for (int nt = 0; nt < 4; nt++)
#pragma unroll
      for (int e = 0; e < 4; e++) c[mt][nt][e] = 0.f;

  for (int ck = 0; ck < 16; ck++) {
    __syncthreads();
    // load + split attn chunk (128 x 64 fp32 -> bf16 hi/lo)
#pragma unroll
    for (int t = 0; t < 4; t++) {
      int idx = tid + 256 * t;
      int rr = idx >> 3, seg = idx & 7;
      const float* src = A + (size_t)(i0 + rr) * 1024 + ck * 64 + seg * 8;
      float4 f0 = *(const float4*)src;
      float4 f1 = *(const float4*)(src + 4);
      B16x8 hh, ll;
      split2(f0.x, hh.h[0], ll.h[0]); split2(f0.y, hh.h[1], ll.h[1]);
      split2(f0.z, hh.h[2], ll.h[2]); split2(f0.w, hh.h[3], ll.h[3]);
      split2(f1.x, hh.h[4], ll.h[4]); split2(f1.y, hh.h[5], ll.h[5]);
      split2(f1.z, hh.h[6], ll.h[6]); split2(f1.w, hh.h[7], ll.h[7]);
      int so = rr * LDSTRIDE + seg * 8;
      *(uint4*)(AHs + so) = hh.u;
      *(uint4*)(ALs + so) = ll.u;
    }
    // load v^T chunk (64 x 64 bf16 hi/lo)
#pragma unroll
    for (int t = 0; t < 2; t++) {
      int idx = tid + 256 * t;        // 0..511
      int d = idx >> 3, seg = idx & 7;
      int so = d * LDSTRIDE + seg * 8;
      *(uint4*)(VHs + so) =
          *(const uint4*)(vth + (size_t)d * 1024 + ck * 64 + seg * 8);
      *(uint4*)(VLs + so) =
          *(const uint4*)(vtl + (size_t)d * 1024 + ck * 64 + seg * 8);
    }
    __syncthreads();

#pragma unroll
    for (int kb = 0; kb < 64; kb += 16) {
      uint32_t ah[2][4], al[2][4];
#pragma unroll
      for (int mt = 0; mt < 2; mt++) {
        int row = m_w + mt * 16 + r;
        const __nv_bfloat16* p = AHs + row * LDSTRIDE + kb + kq;
        ah[mt][0] = *(const uint32_t*)p;
        ah[mt][1] = *(const uint32_t*)(p + 8 * LDSTRIDE);
        ah[mt][2] = *(const uint32_t*)(p + 8);
        ah[mt][3] = *(const uint32_t*)(p + 8 * LDSTRIDE + 8);
        const __nv_bfloat16* q = ALs + row * LDSTRIDE + kb + kq;
        al[mt][0] = *(const uint32_t*)q;
        al[mt][1] = *(const uint32_t*)(q + 8 * LDSTRIDE);
        al[mt][2] = *(const uint32_t*)(q + 8);
        al[mt][3] = *(const uint32_t*)(q + 8 * LDSTRIDE + 8);
      }
      uint32_t bhf[4][2], blf[4][2];
#pragma unroll
      for (int nt = 0; nt < 4; nt++) {
        int nrow = n_w + nt * 8 + r;
        const __nv_bfloat16* p = VHs + nrow * LDSTRIDE + kb + kq;
        bhf[nt][0] = *(const uint32_t*)p;
        bhf[nt][1] = *(const uint32_t*)(p + 8);
        const __nv_bfloat16* q = VLs + nrow * LDSTRIDE + kb + kq;
        blf[nt][0] = *(const uint32_t*)q;
        blf[nt][1] = *(const uint32_t*)(q + 8);
      }
#pragma unroll
      for (int mt = 0; mt < 2; mt++)
#pragma unroll
        for (int nt = 0; nt < 4; nt++) {
          mma16816(c[mt][nt], ah[mt], bhf[nt]);
          mma16816(c[mt][nt], ah[mt], blf[nt]);
          mma16816(c[mt][nt], al[mt], bhf[nt]);
        }
    }
  }

#pragma unroll
  for (int mt = 0; mt < 2; mt++) {
#pragma unroll
    for (int nt = 0; nt < 4; nt++) {
      int row = i0 + m_w + mt * 16 + r;
      int col = n_w + nt * 8 + (lane & 3) * 2;
      float* dst = g_oh + ((size_t)bh * 1024 + row) * 64 + col;
      *(float2*)dst = make_float2(c[mt][nt][0], c[mt][nt][1]);
      *(float2*)(dst + 8 * 64) = make_float2(c[mt][nt][2], c[mt][nt][3]);
    }
  }
}

// ---------------- Kernel 5: pe_sum[bh,i,c] = sum_j attn[bh,i,j]*pe[i,j,c] --
__global__ __launch_bounds__(256) void pes_kernel(const float* __restrict__ pe) {
  __shared__ float pe_s[128 * 32];
  __shared__ float a_s[32 * 132];
  int i = blockIdx.x;
  int tid = threadIdx.x;
  int bh = tid >> 3;
  int c4 = tid & 7;
  float4 acc = make_float4(0.f, 0.f, 0.f, 0.f);
  for (int jt = 0; jt < 1024; jt += 128) {
#pragma unroll
    for (int r = 0; r < 4; r++) {
      int idx4 = tid + r * 256;
      int j = idx4 >> 3, cc = idx4 & 7;
      *(float4*)&pe_s[j * 32 + cc * 4] =
          *(const float4*)(pe + ((size_t)i * 1024 + jt + j) * 32 + cc * 4);
      int bb = idx4 >> 5, jj = idx4 & 31;
      *(float4*)&a_s[bb * 132 + jj * 4] =
          *(const float4*)(g_attn + (size_t)bb * NSEQ * NSEQ +
                           (size_t)i * 1024 + jt + jj * 4);
    }
    __syncthreads();
#pragma unroll 4
    for (int j = 0; j < 128; j++) {
      float a = a_s[bh * 132 + j];
      float4 pv = *(const float4*)&pe_s[j * 32 + c4 * 4];
      acc.x += a * pv.x; acc.y += a * pv.y;
      acc.z += a * pv.z; acc.w += a * pv.w;
    }
    __syncthreads();
  }
  *(float4*)&g_pes[((size_t)bh * 1024 + i) * 32 + c4 * 4] = acc;
}

// ---------------- Kernel 6: merged = out_head + pe_sum@Wpe + bpe -----------
__global__ __launch_bounds__(256) void merge_kernel(
    const float* __restrict__ Wpe, const float* __restrict__ bpe) {
  __shared__ float wpe_s[32 * 64];
  __shared__ float pes_s[32 * 32];
  __shared__ float bpe_s[64];
  int bh = blockIdx.x;
  int n0 = blockIdx.y * 32;
  int tid = threadIdx.x;
#pragma unroll
  for (int r = 0; r < 8; r++) wpe_s[tid + r * 256] = Wpe[tid + r * 256];
  if (tid < 64) bpe_s[tid] = bpe[tid];
  {
    int nl = tid >> 3, cc = tid & 7;
    *(float4*)&pes_s[nl * 32 + cc * 4] =
        *(const float4*)(g_pes + ((size_t)bh * 1024 + n0 + nl) * 32 + cc * 4);
  }
  __syncthreads();
  int nl = tid >> 3;
  int d0 = (tid & 7) * 8;
  int b = bh >> 3, h = bh & 7;
  const float* ohp = g_oh + ((size_t)bh * 1024 + n0 + nl) * 64 + d0;
  float o[8];
#pragma unroll
  for (int dd = 0; dd < 8; dd++) o[dd] = bpe_s[d0 + dd] + ohp[dd];
#pragma unroll 8
  for (int c = 0; c < 32; c++) {
    float pv = pes_s[nl * 32 + c];
#pragma unroll
    for (int dd = 0; dd < 8; dd++) o[dd] += pv * wpe_s[c * 64 + d0 + dd];
  }
  float* mp = g_merged + ((size_t)(b * 1024 + n0 + nl)) * 512 + h * 64 + d0;
#pragma unroll
  for (int dd = 0; dd < 8; dd++) mp[dd] = o[dd];
}

// ---------------- Kernel 7: out = merged @ Wproj ----------------------------
__global__ __launch_bounds__(256) void proj_kernel(
    const float* __restrict__ Wproj, float* __restrict__ out) {
  __shared__ float As[16 * 68];
  __shared__ float Bs[16 * 68];
  int tid = threadIdx.x;
  int m0 = blockIdx.x * 64, n0 = blockIdx.y * 64;
  int tx = tid & 15, ty = tid >> 4;
  int lm = tid >> 2, lk = (tid & 3) * 4;
  int bk = tid >> 4, bn = (tid & 15) * 4;
  float acc[4][4] = {};
  for (int kt = 0; kt < 512; kt += 16) {
    float4 av = *(const float4*)(g_merged + (size_t)(m0 + lm) * 512 + kt + lk);
    As[(lk + 0) * 68 + lm] = av.x; As[(lk + 1) * 68 + lm] = av.y;
    As[(lk + 2) * 68 + lm] = av.z; As[(lk + 3) * 68 + lm] = av.w;
    *(float4*)&Bs[bk * 68 + bn] =
        *(const float4*)(Wproj + (kt + bk) * 256 + n0 + bn);
    __syncthreads();
    MICRO16();
    __syncthreads();
  }
#pragma unroll
  for (int i = 0; i < 4; i++) {
    float4 o = make_float4(acc[i][0], acc[i][1], acc[i][2], acc[i][3]);
    *(float4*)&out[(size_t)(m0 + ty * 4 + i) * 256 + n0 + tx * 4] = o;
  }
}

// ---------------- launch -----------------------------------------------------
extern "C" void kernel_launch(void* const* d_in, const int* in_sizes, int n_in,
                              void* d_out, int out_size) {
  const float* x     = (const float*)d_in[0];
  const float* pe    = (const float*)d_in[1];
  const float* Wq    = (const float*)d_in[2];
  const float* Wk    = (const float*)d_in[3];
  const float* Wv    = (const float*)d_in[4];
  const float* bv    = (const float*)d_in[5];
  const float* Wpe   = (const float*)d_in[6];
  const float* bpe   = (const float*)d_in[7];
  const float* Wproj = (const float*)d_in[8];
  float* out = (float*)d_out;

  static int configured = 0;
  if (!configured) {
    cudaFuncSetAttribute(scores_mma, cudaFuncAttributeMaxDynamicSharedMemorySize,
                         S_SMEM_BYTES);
    cudaFuncSetAttribute(av_mma, cudaFuncAttributeMaxDynamicSharedMemorySize,
                         AV_SMEM_BYTES);
    configured = 1;
  }

  qkv_kernel<<<dim3(64, 24), 256>>>(x, Wq, Wk, Wv, bv);
  scores_mma<<<dim3(8, 8, 32), 256, S_SMEM_BYTES>>>();
  softmax_kernel<<<4096, 256>>>();
  av_mma<<<dim3(8, 32), 256, AV_SMEM_BYTES>>>();
  pes_kernel<<<1024, 256>>>(pe);
  merge_kernel<<<dim3(32, 32), 256>>>(Wpe, bpe);
  proj_kernel<<<dim3(64, 4), 256>>>(Wproj, out);
}

// round 4
// speedup vs baseline: 1.4083x; 1.1297x over previous
#include <cuda_runtime.h>
#include <cuda_bf16.h>
#include <cstdint>

#define NSEQ 1024
#define DIM  256
#define HEADS 8
#define EDIM 512
#define HD   64
#define PEC  32
#define BH   32           // B*HEADS
#define ROWS 4096         // B*N

// ---------------- scratch (device globals; no runtime allocation) ----------
__device__ __nv_bfloat16 g_qh[BH * NSEQ * HD];
__device__ __nv_bfloat16 g_ql[BH * NSEQ * HD];
__device__ __nv_bfloat16 g_kh[BH * NSEQ * HD];
__device__ __nv_bfloat16 g_kl[BH * NSEQ * HD];
__device__ __nv_bfloat16 g_vth[BH * HD * NSEQ];   // transposed: [bh][d][n]
__device__ __nv_bfloat16 g_vtl[BH * HD * NSEQ];
__device__ __nv_bfloat16 g_attn_h[(size_t)BH * NSEQ * NSEQ];  // 64 MB
__device__ __nv_bfloat16 g_attn_l[(size_t)BH * NSEQ * NSEQ];  // 64 MB
__device__ float g_oh[BH * NSEQ * HD];
__device__ float g_pes[BH * NSEQ * PEC];
__device__ float g_merged[ROWS * EDIM];

union B16x8 { __nv_bfloat16 h[8]; uint4 u; };
union B16x2 { __nv_bfloat16 h[2]; uint32_t u; };

__device__ __forceinline__ void split2(float x, __nv_bfloat16& h, __nv_bfloat16& l) {
  h = __float2bfloat16_rn(x);
  l = __float2bfloat16_rn(x - __bfloat162float(h));
}

// m16n8k16 bf16 mma with fp32 accumulate (row.col)
__device__ __forceinline__ void mma16816(float* c, const uint32_t* a,
                                         const uint32_t* b) {
  asm volatile(
      "mma.sync.aligned.m16n8k16.row.col.f32.bf16.bf16.f32 "
      "{%0,%1,%2,%3}, {%4,%5,%6,%7}, {%8,%9}, {%0,%1,%2,%3};"
      : "+f"(c[0]), "+f"(c[1]), "+f"(c[2]), "+f"(c[3])
      : "r"(a[0]), "r"(a[1]), "r"(a[2]), "r"(a[3]), "r"(b[0]), "r"(b[1]));
}

#define LDSTRIDE 72   // bf16 units per SMEM row (64 data + 8 pad)
#define PSTRIDE 136   // bf16 units per SMEM row (128 data + 8 pad)

// 4x4 microtile inner product over a 16-deep K slab (fp32 GEMMs)
#define MICRO16()                                                              \
  _Pragma("unroll")                                                            \
  for (int kk = 0; kk < 16; kk++) {                                            \
    float4 a4 = *(const float4*)&As[kk * 68 + ty * 4];                         \
    float4 b4 = *(const float4*)&Bs[kk * 68 + tx * 4];                         \
    acc[0][0] += a4.x * b4.x; acc[0][1] += a4.x * b4.y;                        \
    acc[0][2] += a4.x * b4.z; acc[0][3] += a4.x * b4.w;                        \
    acc[1][0] += a4.y * b4.x; acc[1][1] += a4.y * b4.y;                        \
    acc[1][2] += a4.y * b4.z; acc[1][3] += a4.y * b4.w;                        \
    acc[2][0] += a4.z * b4.x; acc[2][1] += a4.z * b4.y;                        \
    acc[2][2] += a4.z * b4.z; acc[2][3] += a4.z * b4.w;                        \
    acc[3][0] += a4.w * b4.x; acc[3][1] += a4.w * b4.y;                        \
    acc[3][2] += a4.w * b4.z; acc[3][3] += a4.w * b4.w;                        \
  }

// ---------------- Kernel 1: fused QKV projection ---------------------------
__global__ __launch_bounds__(256) void qkv_kernel(
    const float* __restrict__ x, const float* __restrict__ Wq,
    const float* __restrict__ Wk, const float* __restrict__ Wv,
    const float* __restrict__ bv) {
  __shared__ float As[16 * 68];
  __shared__ float Bs[16 * 68];
  int tid = threadIdx.x;
  int m0 = blockIdx.x * 64;
  int gc0 = blockIdx.y * 64;
  int sel = gc0 / 512;
  int e0 = gc0 % 512;
  int h = e0 / 64;
  const float* Bmat = (sel == 0) ? Wq : (sel == 1) ? Wk : Wv;
  int tx = tid & 15, ty = tid >> 4;
  int lm = tid >> 2, lk = (tid & 3) * 4;
  int bk = tid >> 4, bn = (tid & 15) * 4;
  float acc[4][4] = {};
  for (int kt = 0; kt < 256; kt += 16) {
    float4 av = *(const float4*)(x + (m0 + lm) * 256 + kt + lk);
    As[(lk + 0) * 68 + lm] = av.x; As[(lk + 1) * 68 + lm] = av.y;
    As[(lk + 2) * 68 + lm] = av.z; As[(lk + 3) * 68 + lm] = av.w;
    *(float4*)&Bs[bk * 68 + bn] =
        *(const float4*)(Bmat + (kt + bk) * 512 + e0 + bn);
    __syncthreads();
    MICRO16();
    __syncthreads();
  }
#pragma unroll
  for (int i = 0; i < 4; i++) {
    int gr = m0 + ty * 4 + i;
    int b = gr >> 10, n = gr & 1023;
    int bh = b * 8 + h;
#pragma unroll
    for (int j = 0; j < 4; j++) {
      int c = tx * 4 + j;
      float v = acc[i][j];
      __nv_bfloat16 hi, lo;
      if (sel == 0) {
        v *= 0.125f;
        split2(v, hi, lo);
        size_t idx = ((size_t)bh * 1024 + n) * 64 + c;
        g_qh[idx] = hi; g_ql[idx] = lo;
      } else if (sel == 1) {
        split2(v, hi, lo);
        size_t idx = ((size_t)bh * 1024 + n) * 64 + c;
        g_kh[idx] = hi; g_kl[idx] = lo;
      } else {
        v += bv[e0 + c];
        split2(v, hi, lo);
        size_t idx = ((size_t)bh * 64 + c) * 1024 + n;   // transposed
        g_vth[idx] = hi; g_vtl[idx] = lo;
      }
    }
  }
}

// ---------------- Kernel 2: fused scores + softmax -> split bf16 attn -------
// CTA = 32 query rows x FULL 1024-col row, K=64. grid (32 i-tiles, 32 bh).
// 8 warps: 2 along m (16 rows each), 4 along n (32 cols per 128-chunk each).
__global__ __launch_bounds__(256) void scoresm() {
  __shared__ __nv_bfloat16 QH[32 * LDSTRIDE], QL[32 * LDSTRIDE];
  __shared__ __nv_bfloat16 KH[128 * LDSTRIDE], KL[128 * LDSTRIDE];
  __shared__ float red[32][4];

  int tid = threadIdx.x;
  int wid = tid >> 5, lane = tid & 31;
  int bh = blockIdx.y;
  int i0 = blockIdx.x * 32;

  const __nv_bfloat16* qh = g_qh + (size_t)bh * NSEQ * HD;
  const __nv_bfloat16* ql = g_ql + (size_t)bh * NSEQ * HD;
  const __nv_bfloat16* kh = g_kh + (size_t)bh * NSEQ * HD;
  const __nv_bfloat16* kl = g_kl + (size_t)bh * NSEQ * HD;

  // stage q (32 x 64, hi/lo): 256 uint4 each, one per thread
  {
    int r = tid >> 3, seg = tid & 7;
    int so = r * LDSTRIDE + seg * 8;
    *(uint4*)(QH + so) = *(const uint4*)(qh + (i0 + r) * 64 + seg * 8);
    *(uint4*)(QL + so) = *(const uint4*)(ql + (i0 + r) * 64 + seg * 8);
  }

  int mw = (wid & 1) * 16;        // m-warp base row (0 or 16)
  int nwb = (wid >> 1) * 32;      // n-warp base col within each 128-chunk
  int r = lane >> 2, kq = (lane & 3) * 2;

  uint32_t ah[4][4], al[4][4];
  float acc[8][4][4];
#pragma unroll
  for (int jc = 0; jc < 8; jc++)
#pragma unroll
    for (int nt = 0; nt < 4; nt++)
#pragma unroll
      for (int e = 0; e < 4; e++) acc[jc][nt][e] = 0.f;

#pragma unroll
  for (int jc = 0; jc < 8; jc++) {
    if (jc) __syncthreads();
    // stage k chunk (128 x 64, hi/lo)
#pragma unroll
    for (int t = 0; t < 4; t++) {
      int idx = tid + 256 * t;
      int rr = idx >> 3, seg = idx & 7;
      int so = rr * LDSTRIDE + seg * 8;
      *(uint4*)(KH + so) = *(const uint4*)(kh + (jc * 128 + rr) * 64 + seg * 8);
      *(uint4*)(KL + so) = *(const uint4*)(kl + (jc * 128 + rr) * 64 + seg * 8);
    }
    __syncthreads();
    if (jc == 0) {
      // hoist a-frags for all 4 k-steps (q smem now valid)
#pragma unroll
      for (int kb = 0; kb < 4; kb++) {
        const __nv_bfloat16* p = QH + (mw + r) * LDSTRIDE + kb * 16 + kq;
        ah[kb][0] = *(const uint32_t*)p;
        ah[kb][1] = *(const uint32_t*)(p + 8 * LDSTRIDE);
        ah[kb][2] = *(const uint32_t*)(p + 8);
        ah[kb][3] = *(const uint32_t*)(p + 8 * LDSTRIDE + 8);
        const __nv_bfloat16* q = QL + (mw + r) * LDSTRIDE + kb * 16 + kq;
        al[kb][0] = *(const uint32_t*)q;
        al[kb][1] = *(const uint32_t*)(q + 8 * LDSTRIDE);
        al[kb][2] = *(const uint32_t*)(q + 8);
        al[kb][3] = *(const uint32_t*)(q + 8 * LDSTRIDE + 8);
      }
    }
#pragma unroll
    for (int kb = 0; kb < 4; kb++) {
#pragma unroll
      for (int nt = 0; nt < 4; nt++) {
        int nrow = nwb + nt * 8 + r;
        const __nv_bfloat16* p = KH + nrow * LDSTRIDE + kb * 16 + kq;
        uint32_t bhf[2] = {*(const uint32_t*)p, *(const uint32_t*)(p + 8)};
        const __nv_bfloat16* q = KL + nrow * LDSTRIDE + kb * 16 + kq;
        uint32_t blf[2] = {*(const uint32_t*)q, *(const uint32_t*)(q + 8)};
        mma16816(acc[jc][nt], ah[kb], bhf);
        mma16816(acc[jc][nt], ah[kb], blf);
        mma16816(acc[jc][nt], al[kb], bhf);
      }
    }
  }

  // ---- row softmax across the full 1024 columns ----
  int r0 = mw + r, r1 = r0 + 8;
  float m0 = -1e30f, m1 = -1e30f;
#pragma unroll
  for (int jc = 0; jc < 8; jc++)
#pragma unroll
    for (int nt = 0; nt < 4; nt++) {
      m0 = fmaxf(m0, fmaxf(acc[jc][nt][0], acc[jc][nt][1]));
      m1 = fmaxf(m1, fmaxf(acc[jc][nt][2], acc[jc][nt][3]));
    }
#pragma unroll
  for (int o = 1; o <= 2; o <<= 1) {
    m0 = fmaxf(m0, __shfl_xor_sync(~0u, m0, o));
    m1 = fmaxf(m1, __shfl_xor_sync(~0u, m1, o));
  }
  if ((lane & 3) == 0) { red[r0][wid >> 1] = m0; red[r1][wid >> 1] = m1; }
  __syncthreads();
  m0 = fmaxf(fmaxf(red[r0][0], red[r0][1]), fmaxf(red[r0][2], red[r0][3]));
  m1 = fmaxf(fmaxf(red[r1][0], red[r1][1]), fmaxf(red[r1][2], red[r1][3]));
  __syncthreads();

  float s0 = 0.f, s1 = 0.f;
#pragma unroll
  for (int jc = 0; jc < 8; jc++)
#pragma unroll
    for (int nt = 0; nt < 4; nt++) {
      acc[jc][nt][0] = __expf(acc[jc][nt][0] - m0);
      acc[jc][nt][1] = __expf(acc[jc][nt][1] - m0);
      acc[jc][nt][2] = __expf(acc[jc][nt][2] - m1);
      acc[jc][nt][3] = __expf(acc[jc][nt][3] - m1);
      s0 += acc[jc][nt][0] + acc[jc][nt][1];
      s1 += acc[jc][nt][2] + acc[jc][nt][3];
    }
#pragma unroll
  for (int o = 1; o <= 2; o <<= 1) {
    s0 += __shfl_xor_sync(~0u, s0, o);
    s1 += __shfl_xor_sync(~0u, s1, o);
  }
  if ((lane & 3) == 0) { red[r0][wid >> 1] = s0; red[r1][wid >> 1] = s1; }
  __syncthreads();
  s0 = red[r0][0] + red[r0][1] + red[r0][2] + red[r0][3];
  s1 = red[r1][0] + red[r1][1] + red[r1][2] + red[r1][3];
  float inv0 = 1.f / s0, inv1 = 1.f / s1;

  size_t base0 = (((size_t)bh << 10) + (i0 + r0)) << 10;
  size_t base1 = (((size_t)bh << 10) + (i0 + r1)) << 10;
#pragma unroll
  for (int jc = 0; jc < 8; jc++) {
#pragma unroll
    for (int nt = 0; nt < 4; nt++) {
      int col = jc * 128 + nwb + nt * 8 + (lane & 3) * 2;
      float e0 = acc[jc][nt][0] * inv0, e1 = acc[jc][nt][1] * inv0;
      float e2 = acc[jc][nt][2] * inv1, e3 = acc[jc][nt][3] * inv1;
      B16x2 hp, lp;
      split2(e0, hp.h[0], lp.h[0]); split2(e1, hp.h[1], lp.h[1]);
      *(uint32_t*)(g_attn_h + base0 + col) = hp.u;
      *(uint32_t*)(g_attn_l + base0 + col) = lp.u;
      split2(e2, hp.h[0], lp.h[0]); split2(e3, hp.h[1], lp.h[1]);
      *(uint32_t*)(g_attn_h + base1 + col) = hp.u;
      *(uint32_t*)(g_attn_l + base1 + col) = lp.u;
    }
  }
}

// ---------------- Kernel 3: out_head = attn @ v via mma.sync ----------------
// CTA = 128 (i) x 64 (d), K = 1024 in 16 chunks of 64. grid (8, 32).
#define AV_SMEM_BYTES ((2 * 128 + 2 * 64) * LDSTRIDE * 2)
__global__ __launch_bounds__(256) void av_mma() {
  extern __shared__ __nv_bfloat16 sm[];
  __nv_bfloat16* AHs = sm;
  __nv_bfloat16* ALs = AHs + 128 * LDSTRIDE;
  __nv_bfloat16* VHs = ALs + 128 * LDSTRIDE;
  __nv_bfloat16* VLs = VHs + 64 * LDSTRIDE;

  int tid = threadIdx.x;
  int wid = tid >> 5, lane = tid & 31;
  int bh = blockIdx.y;
  int i0 = blockIdx.x * 128;

  const __nv_bfloat16* vth = g_vth + (size_t)bh * HD * NSEQ;
  const __nv_bfloat16* vtl = g_vtl + (size_t)bh * HD * NSEQ;

  int m_w = (wid >> 1) * 32;          // 4 warps along m
  int n_w = (wid & 1) * 32;           // 2 warps along n
  int r = lane >> 2, kq = (lane & 3) * 2;

  float c[2][4][4];
#pragma unroll
  for (int mt = 0; mt < 2; mt++)
#pragma unroll
    for (int nt = 0; nt < 4; nt++)
#pragma unroll
      for (int e = 0; e < 4; e++) c[mt][nt][e] = 0.f;

  for (int ck = 0; ck < 16; ck++) {
    __syncthreads();
    // stage attn chunk (128 x 64 bf16 hi/lo, pre-split)
#pragma unroll
    for (int t = 0; t < 4; t++) {
      int idx = tid + 256 * t;
      int rr = idx >> 3, seg = idx & 7;
      size_t gsrc = ((((size_t)bh << 10) + i0 + rr) << 10) + ck * 64 + seg * 8;
      int so = rr * LDSTRIDE + seg * 8;
      *(uint4*)(AHs + so) = *(const uint4*)(g_attn_h + gsrc);
      *(uint4*)(ALs + so) = *(const uint4*)(g_attn_l + gsrc);
    }
    // stage v^T chunk (64 x 64 bf16 hi/lo)
#pragma unroll
    for (int t = 0; t < 2; t++) {
      int idx = tid + 256 * t;        // 0..511
      int d = idx >> 3, seg = idx & 7;
      int so = d * LDSTRIDE + seg * 8;
      *(uint4*)(VHs + so) =
          *(const uint4*)(vth + (size_t)d * 1024 + ck * 64 + seg * 8);
      *(uint4*)(VLs + so) =
          *(const uint4*)(vtl + (size_t)d * 1024 + ck * 64 + seg * 8);
    }
    __syncthreads();

#pragma unroll
    for (int kb = 0; kb < 64; kb += 16) {
      uint32_t ah[2][4], al[2][4];
#pragma unroll
      for (int mt = 0; mt < 2; mt++) {
        int row = m_w + mt * 16 + r;
        const __nv_bfloat16* p = AHs + row * LDSTRIDE + kb + kq;
        ah[mt][0] = *(const uint32_t*)p;
        ah[mt][1] = *(const uint32_t*)(p + 8 * LDSTRIDE);
        ah[mt][2] = *(const uint32_t*)(p + 8);
        ah[mt][3] = *(const uint32_t*)(p + 8 * LDSTRIDE + 8);
        const __nv_bfloat16* q = ALs + row * LDSTRIDE + kb + kq;
        al[mt][0] = *(const uint32_t*)q;
        al[mt][1] = *(const uint32_t*)(q + 8 * LDSTRIDE);
        al[mt][2] = *(const uint32_t*)(q + 8);
        al[mt][3] = *(const uint32_t*)(q + 8 * LDSTRIDE + 8);
      }
      uint32_t bhf[4][2], blf[4][2];
#pragma unroll
      for (int nt = 0; nt < 4; nt++) {
        int nrow = n_w + nt * 8 + r;
        const __nv_bfloat16* p = VHs + nrow * LDSTRIDE + kb + kq;
        bhf[nt][0] = *(const uint32_t*)p;
        bhf[nt][1] = *(const uint32_t*)(p + 8);
        const __nv_bfloat16* q = VLs + nrow * LDSTRIDE + kb + kq;
        blf[nt][0] = *(const uint32_t*)q;
        blf[nt][1] = *(const uint32_t*)(q + 8);
      }
#pragma unroll
      for (int mt = 0; mt < 2; mt++)
#pragma unroll
        for (int nt = 0; nt < 4; nt++) {
          mma16816(c[mt][nt], ah[mt], bhf[nt]);
          mma16816(c[mt][nt], ah[mt], blf[nt]);
          mma16816(c[mt][nt], al[mt], bhf[nt]);
        }
    }
  }

#pragma unroll
  for (int mt = 0; mt < 2; mt++) {
#pragma unroll
    for (int nt = 0; nt < 4; nt++) {
      int row = i0 + m_w + mt * 16 + r;
      int col = n_w + nt * 8 + (lane & 3) * 2;
      float* dst = g_oh + ((size_t)bh * 1024 + row) * 64 + col;
      *(float2*)dst = make_float2(c[mt][nt][0], c[mt][nt][1]);
      *(float2*)(dst + 8 * 64) = make_float2(c[mt][nt][2], c[mt][nt][3]);
    }
  }
}

// ---------------- Kernel 4: pe_sum via mma ----------------------------------
// Per query index i: pe_sum[.,i,.] = attn[:,i,:](32bh x 1024j) @ pe[i](1024j x 32c)
// CTA per i, M=32(bh) N=32(c) K=1024 in 8 chunks of 128. 8 warps: 2m x 4n.
__global__ __launch_bounds__(256) void pes_mma(const float* __restrict__ pe) {
  __shared__ __nv_bfloat16 AH[32 * PSTRIDE], AL[32 * PSTRIDE];
  __shared__ __nv_bfloat16 PH[32 * PSTRIDE], PL[32 * PSTRIDE];

  int tid = threadIdx.x;
  int wid = tid >> 5, lane = tid & 31;
  int i = blockIdx.x;
  int mw = (wid & 1) * 16;        // bh rows
  int nw = (wid >> 1) * 8;        // c cols
  int r = lane >> 2, kq = (lane & 3) * 2;

  float acc[4] = {};
  for (int kc = 0; kc < 8; kc++) {
    if (kc) __syncthreads();
    // stage attn rows: 32 bh x 128 j (hi/lo)
#pragma unroll
    for (int t = 0; t < 2; t++) {
      int idx = tid + 256 * t;        // 0..511
      int row = idx >> 4, seg = idx & 15;
      size_t gsrc = ((size_t)row << 20) + ((size_t)i << 10) + kc * 128 + seg * 8;
      int so = row * PSTRIDE + seg * 8;
      *(uint4*)(AH + so) = *(const uint4*)(g_attn_h + gsrc);
      *(uint4*)(AL + so) = *(const uint4*)(g_attn_l + gsrc);
    }
    // stage pe[i] chunk transposed + split: peT[c][j]
#pragma unroll
    for (int t = 0; t < 4; t++) {
      int idx = tid + 256 * t;        // 0..1023
      int j = idx >> 3, c4 = idx & 7;
      float4 v = *(const float4*)(
          pe + (((size_t)i << 10) + kc * 128 + j) * 32 + c4 * 4);
      __nv_bfloat16 h, l;
      split2(v.x, h, l); PH[(c4 * 4 + 0) * PSTRIDE + j] = h; PL[(c4 * 4 + 0) * PSTRIDE + j] = l;
      split2(v.y, h, l); PH[(c4 * 4 + 1) * PSTRIDE + j] = h; PL[(c4 * 4 + 1) * PSTRIDE + j] = l;
      split2(v.z, h, l); PH[(c4 * 4 + 2) * PSTRIDE + j] = h; PL[(c4 * 4 + 2) * PSTRIDE + j] = l;
      split2(v.w, h, l); PH[(c4 * 4 + 3) * PSTRIDE + j] = h; PL[(c4 * 4 + 3) * PSTRIDE + j] = l;
    }
    __syncthreads();
#pragma unroll
    for (int kb = 0; kb < 8; kb++) {
      const __nv_bfloat16* p = AH + (mw + r) * PSTRIDE + kb * 16 + kq;
      uint32_t ah4[4] = {*(const uint32_t*)p,
                         *(const uint32_t*)(p + 8 * PSTRIDE),
                         *(const uint32_t*)(p + 8),
                         *(const uint32_t*)(p + 8 * PSTRIDE + 8)};
      const __nv_bfloat16* q = AL + (mw + r) * PSTRIDE + kb * 16 + kq;
      uint32_t al4[4] = {*(const uint32_t*)q,
                         *(const uint32_t*)(q + 8 * PSTRIDE),
                         *(const uint32_t*)(q + 8),
                         *(const uint32_t*)(q + 8 * PSTRIDE + 8)};
      const __nv_bfloat16* pb = PH + (nw + r) * PSTRIDE + kb * 16 + kq;
      uint32_t bh2[2] = {*(const uint32_t*)pb, *(const uint32_t*)(pb + 8)};
      const __nv_bfloat16* qb = PL + (nw + r) * PSTRIDE + kb * 16 + kq;
      uint32_t bl2[2] = {*(const uint32_t*)qb, *(const uint32_t*)(qb + 8)};
      mma16816(acc, ah4, bh2);
      mma16816(acc, ah4, bl2);
      mma16816(acc, al4, bh2);
    }
  }
  int c = nw + (lane & 3) * 2;
  int b0 = mw + r, b1 = b0 + 8;
  *(float2*)&g_pes[(((size_t)b0 << 10) + i) * 32 + c] = make_float2(acc[0], acc[1]);
  *(float2*)&g_pes[(((size_t)b1 << 10) + i) * 32 + c] = make_float2(acc[2], acc[3]);
}

// ---------------- Kernel 5: merged = out_head + pe_sum@Wpe + bpe -----------
__global__ __launch_bounds__(256) void merge_kernel(
    const float* __restrict__ Wpe, const float* __restrict__ bpe) {
  __shared__ float wpe_s[32 * 64];
  __shared__ float pes_s[32 * 32];
  __shared__ float bpe_s[64];
  int bh = blockIdx.x;
  int n0 = blockIdx.y * 32;
  int tid = threadIdx.x;
#pragma unroll
  for (int r = 0; r < 8; r++) wpe_s[tid + r * 256] = Wpe[tid + r * 256];
  if (tid < 64) bpe_s[tid] = bpe[tid];
  {
    int nl = tid >> 3, cc = tid & 7;
    *(float4*)&pes_s[nl * 32 + cc * 4] =
        *(const float4*)(g_pes + ((size_t)bh * 1024 + n0 + nl) * 32 + cc * 4);
  }
  __syncthreads();
  int nl = tid >> 3;
  int d0 = (tid & 7) * 8;
  int b = bh >> 3, h = bh & 7;
  const float* ohp = g_oh + ((size_t)bh * 1024 + n0 + nl) * 64 + d0;
  float o[8];
#pragma unroll
  for (int dd = 0; dd < 8; dd++) o[dd] = bpe_s[d0 + dd] + ohp[dd];
#pragma unroll 8
  for (int c = 0; c < 32; c++) {
    float pv = pes_s[nl * 32 + c];
#pragma unroll
    for (int dd = 0; dd < 8; dd++) o[dd] += pv * wpe_s[c * 64 + d0 + dd];
  }
  float* mp = g_merged + ((size_t)(b * 1024 + n0 + nl)) * 512 + h * 64 + d0;
#pragma unroll
  for (int dd = 0; dd < 8; dd++) mp[dd] = o[dd];
}

// ---------------- Kernel 6: out = merged @ Wproj ----------------------------
__global__ __launch_bounds__(256) void proj_kernel(
    const float* __restrict__ Wproj, float* __restrict__ out) {
  __shared__ float As[16 * 68];
  __shared__ float Bs[16 * 68];
  int tid = threadIdx.x;
  int m0 = blockIdx.x * 64, n0 = blockIdx.y * 64;
  int tx = tid & 15, ty = tid >> 4;
  int lm = tid >> 2, lk = (tid & 3) * 4;
  int bk = tid >> 4, bn = (tid & 15) * 4;
  float acc[4][4] = {};
  for (int kt = 0; kt < 512; kt += 16) {
    float4 av = *(const float4*)(g_merged + (size_t)(m0 + lm) * 512 + kt + lk);
    As[(lk + 0) * 68 + lm] = av.x; As[(lk + 1) * 68 + lm] = av.y;
    As[(lk + 2) * 68 + lm] = av.z; As[(lk + 3) * 68 + lm] = av.w;
    *(float4*)&Bs[bk * 68 + bn] =
        *(const float4*)(Wproj + (kt + bk) * 256 + n0 + bn);
    __syncthreads();
    MICRO16();
    __syncthreads();
  }
#pragma unroll
  for (int i = 0; i < 4; i++) {
    float4 o = make_float4(acc[i][0], acc[i][1], acc[i][2], acc[i][3]);
    *(float4*)&out[(size_t)(m0 + ty * 4 + i) * 256 + n0 + tx * 4] = o;
  }
}

// ---------------- launch -----------------------------------------------------
extern "C" void kernel_launch(void* const* d_in, const int* in_sizes, int n_in,
                              void* d_out, int out_size) {
  const float* x     = (const float*)d_in[0];
  const float* pe    = (const float*)d_in[1];
  const float* Wq    = (const float*)d_in[2];
  const float* Wk    = (const float*)d_in[3];
  const float* Wv    = (const float*)d_in[4];
  const float* bv    = (const float*)d_in[5];
  const float* Wpe   = (const float*)d_in[6];
  const float* bpe   = (const float*)d_in[7];
  const float* Wproj = (const float*)d_in[8];
  float* out = (float*)d_out;

  static int configured = 0;
  if (!configured) {
    cudaFuncSetAttribute(av_mma, cudaFuncAttributeMaxDynamicSharedMemorySize,
                         AV_SMEM_BYTES);
    configured = 1;
  }

  qkv_kernel<<<dim3(64, 24), 256>>>(x, Wq, Wk, Wv, bv);
  scoresm<<<dim3(32, 32), 256>>>();
  av_mma<<<dim3(8, 32), 256, AV_SMEM_BYTES>>>();
  pes_mma<<<1024, 256>>>(pe);
  merge_kernel<<<dim3(32, 32), 256>>>(Wpe, bpe);
  proj_kernel<<<dim3(64, 4), 256>>>(Wproj, out);
}

// round 5
// speedup vs baseline: 1.8493x; 1.3132x over previous
#include <cuda_runtime.h>
#include <cuda_bf16.h>
#include <cstdint>

#define NSEQ 1024
#define DIM  256
#define HEADS 8
#define EDIM 512
#define HD   64
#define PEC  32
#define BH   32           // B*HEADS
#define ROWS 4096         // B*N

// ---------------- scratch (device globals; no runtime allocation) ----------
__device__ __nv_bfloat16 g_xh[ROWS * DIM], g_xl[ROWS * DIM];
__device__ __nv_bfloat16 g_wth[1536 * 256], g_wtl[1536 * 256];   // [n][k]
__device__ __nv_bfloat16 g_wpth[256 * 512], g_wptl[256 * 512];   // [n][k]
__device__ __nv_bfloat16 g_qh[BH * NSEQ * HD];
__device__ __nv_bfloat16 g_ql[BH * NSEQ * HD];
__device__ __nv_bfloat16 g_kh[BH * NSEQ * HD];
__device__ __nv_bfloat16 g_kl[BH * NSEQ * HD];
__device__ __nv_bfloat16 g_vth[BH * HD * NSEQ];   // transposed: [bh][d][n]
__device__ __nv_bfloat16 g_vtl[BH * HD * NSEQ];
__device__ __nv_bfloat16 g_attn_h[(size_t)BH * NSEQ * NSEQ];  // 64 MB
__device__ __nv_bfloat16 g_attn_l[(size_t)BH * NSEQ * NSEQ];  // 64 MB
__device__ float g_oh[BH * NSEQ * HD];
__device__ float g_pes[BH * NSEQ * PEC];
__device__ __nv_bfloat16 g_mh[ROWS * EDIM], g_ml[ROWS * EDIM];

union B16x8 { __nv_bfloat16 h[8]; uint4 u; };
union B16x4 { __nv_bfloat16 h[4]; uint2 u; };
union B16x2 { __nv_bfloat16 h[2]; uint32_t u; };

__device__ __forceinline__ void split2(float x, __nv_bfloat16& h, __nv_bfloat16& l) {
  h = __float2bfloat16_rn(x);
  l = __float2bfloat16_rn(x - __bfloat162float(h));
}

// m16n8k16 bf16 mma with fp32 accumulate (row.col)
__device__ __forceinline__ void mma16816(float* c, const uint32_t* a,
                                         const uint32_t* b) {
  asm volatile(
      "mma.sync.aligned.m16n8k16.row.col.f32.bf16.bf16.f32 "
      "{%0,%1,%2,%3}, {%4,%5,%6,%7}, {%8,%9}, {%0,%1,%2,%3};"
      : "+f"(c[0]), "+f"(c[1]), "+f"(c[2]), "+f"(c[3])
      : "r"(a[0]), "r"(a[1]), "r"(a[2]), "r"(a[3]), "r"(b[0]), "r"(b[1]));
}

#define LDSTRIDE 72   // bf16 units per SMEM row (64 data + 8 pad)
#define PSTRIDE 136   // bf16 units per SMEM row (128 data + 8 pad)
#define GEMM_SMEM_BYTES ((2 * 128 + 2 * 64) * LDSTRIDE * 2)   // 55296

// ---------------- prep: split x into bf16 hi/lo ------------------------------
__global__ __launch_bounds__(256) void split_x(const float* __restrict__ x) {
  int idx = (blockIdx.x * 256 + threadIdx.x) * 4;
  float4 v = *(const float4*)(x + idx);
  B16x4 hh, ll;
  split2(v.x, hh.h[0], ll.h[0]); split2(v.y, hh.h[1], ll.h[1]);
  split2(v.z, hh.h[2], ll.h[2]); split2(v.w, hh.h[3], ll.h[3]);
  *(uint2*)&g_xh[idx] = hh.u;
  *(uint2*)&g_xl[idx] = ll.u;
}

// ---------------- prep: transpose + split weights -----------------------------
__global__ __launch_bounds__(256) void prep_w(
    const float* __restrict__ Wq, const float* __restrict__ Wk,
    const float* __restrict__ Wv, const float* __restrict__ Wproj) {
  int id = blockIdx.x * 256 + threadIdx.x;
  if (id < 98304) {                 // WT: 1536 n x 64 k-groups
    int n = id >> 6, k0 = (id & 63) * 4;
    int sel = n >> 9, col = n & 511;
    const float* W = (sel == 0) ? Wq : (sel == 1) ? Wk : Wv;
#pragma unroll
    for (int q = 0; q < 4; q++) {
      float v = W[(k0 + q) * 512 + col];
      split2(v, g_wth[n * 256 + k0 + q], g_wtl[n * 256 + k0 + q]);
    }
  } else {                          // WprojT: 256 n x 128 k-groups
    int id2 = id - 98304;
    int n = id2 >> 7, k0 = (id2 & 127) * 4;
#pragma unroll
    for (int q = 0; q < 4; q++) {
      float v = Wproj[(k0 + q) * 256 + n];
      split2(v, g_wpth[n * 512 + k0 + q], g_wptl[n * 512 + k0 + q]);
    }
  }
}

// ---------------- Kernel 1: QKV projection via mma.sync ---------------------
// M=4096, N=1536, K=256. CTA 128m x 64n, grid (32, 24). 8 warps: 4m x 2n.
__global__ __launch_bounds__(256) void qkv_mma(const float* __restrict__ bv) {
  extern __shared__ __nv_bfloat16 sm[];
  __nv_bfloat16* XH = sm;
  __nv_bfloat16* XL = XH + 128 * LDSTRIDE;
  __nv_bfloat16* WH = XL + 128 * LDSTRIDE;
  __nv_bfloat16* WL = WH + 64 * LDSTRIDE;

  int tid = threadIdx.x;
  int wid = tid >> 5, lane = tid & 31;
  int m0 = blockIdx.x * 128;
  int n0 = blockIdx.y * 64;
  int sel = n0 / 512;
  int e0 = n0 % 512;
  int h = e0 / 64;

  int m_w = (wid >> 1) * 32, n_w = (wid & 1) * 32;
  int r = lane >> 2, kq = (lane & 3) * 2;

  float c[2][4][4];
#pragma unroll
  for (int mt = 0; mt < 2; mt++)
#pragma unroll
    for (int nt = 0; nt < 4; nt++)
#pragma unroll
      for (int e = 0; e < 4; e++) c[mt][nt][e] = 0.f;

  for (int ck = 0; ck < 4; ck++) {
    if (ck) __syncthreads();
#pragma unroll
    for (int t = 0; t < 4; t++) {
      int idx = tid + 256 * t;
      int rr = idx >> 3, seg = idx & 7;
      int so = rr * LDSTRIDE + seg * 8;
      size_t gs = (size_t)(m0 + rr) * 256 + ck * 64 + seg * 8;
      *(uint4*)(XH + so) = *(const uint4*)(g_xh + gs);
      *(uint4*)(XL + so) = *(const uint4*)(g_xl + gs);
    }
#pragma unroll
    for (int t = 0; t < 2; t++) {
      int idx = tid + 256 * t;
      int d = idx >> 3, seg = idx & 7;
      int so = d * LDSTRIDE + seg * 8;
      size_t gs = (size_t)(n0 + d) * 256 + ck * 64 + seg * 8;
      *(uint4*)(WH + so) = *(const uint4*)(g_wth + gs);
      *(uint4*)(WL + so) = *(const uint4*)(g_wtl + gs);
    }
    __syncthreads();
#pragma unroll
    for (int kb = 0; kb < 64; kb += 16) {
      uint32_t ah[2][4], al[2][4];
#pragma unroll
      for (int mt = 0; mt < 2; mt++) {
        int row = m_w + mt * 16 + r;
        const __nv_bfloat16* p = XH + row * LDSTRIDE + kb + kq;
        ah[mt][0] = *(const uint32_t*)p;
        ah[mt][1] = *(const uint32_t*)(p + 8 * LDSTRIDE);
        ah[mt][2] = *(const uint32_t*)(p + 8);
        ah[mt][3] = *(const uint32_t*)(p + 8 * LDSTRIDE + 8);
        const __nv_bfloat16* q = XL + row * LDSTRIDE + kb + kq;
        al[mt][0] = *(const uint32_t*)q;
        al[mt][1] = *(const uint32_t*)(q + 8 * LDSTRIDE);
        al[mt][2] = *(const uint32_t*)(q + 8);
        al[mt][3] = *(const uint32_t*)(q + 8 * LDSTRIDE + 8);
      }
      uint32_t bhf[4][2], blf[4][2];
#pragma unroll
      for (int nt = 0; nt < 4; nt++) {
        int nrow = n_w + nt * 8 + r;
        const __nv_bfloat16* p = WH + nrow * LDSTRIDE + kb + kq;
        bhf[nt][0] = *(const uint32_t*)p;
        bhf[nt][1] = *(const uint32_t*)(p + 8);
        const __nv_bfloat16* q = WL + nrow * LDSTRIDE + kb + kq;
        blf[nt][0] = *(const uint32_t*)q;
        blf[nt][1] = *(const uint32_t*)(q + 8);
      }
#pragma unroll
      for (int mt = 0; mt < 2; mt++)
#pragma unroll
        for (int nt = 0; nt < 4; nt++) {
          mma16816(c[mt][nt], ah[mt], bhf[nt]);
          mma16816(c[mt][nt], ah[mt], blf[nt]);
          mma16816(c[mt][nt], al[mt], bhf[nt]);
        }
    }
  }

#pragma unroll
  for (int mt = 0; mt < 2; mt++) {
#pragma unroll
    for (int nt = 0; nt < 4; nt++) {
      int colw = n_w + nt * 8 + (lane & 3) * 2;   // 0..62, even
      int d = colw;                                // channel within head
      int e = e0 + colw;
#pragma unroll
      for (int half = 0; half < 2; half++) {
        int row = m0 + m_w + mt * 16 + r + half * 8;
        float v0 = c[mt][nt][half * 2 + 0];
        float v1 = c[mt][nt][half * 2 + 1];
        int b = row >> 10, n = row & 1023;
        int bh = b * 8 + h;
        if (sel == 0) {
          v0 *= 0.125f; v1 *= 0.125f;
          B16x2 hp, lp;
          split2(v0, hp.h[0], lp.h[0]); split2(v1, hp.h[1], lp.h[1]);
          size_t idx = ((size_t)bh * 1024 + n) * 64 + d;
          *(uint32_t*)&g_qh[idx] = hp.u;
          *(uint32_t*)&g_ql[idx] = lp.u;
        } else if (sel == 1) {
          B16x2 hp, lp;
          split2(v0, hp.h[0], lp.h[0]); split2(v1, hp.h[1], lp.h[1]);
          size_t idx = ((size_t)bh * 1024 + n) * 64 + d;
          *(uint32_t*)&g_kh[idx] = hp.u;
          *(uint32_t*)&g_kl[idx] = lp.u;
        } else {
          v0 += bv[e]; v1 += bv[e + 1];
          __nv_bfloat16 hh, ll;
          split2(v0, hh, ll);
          size_t i0v = ((size_t)bh * 64 + d) * 1024 + n;
          g_vth[i0v] = hh; g_vtl[i0v] = ll;
          split2(v1, hh, ll);
          size_t i1v = ((size_t)bh * 64 + d + 1) * 1024 + n;
          g_vth[i1v] = hh; g_vtl[i1v] = ll;
        }
      }
    }
  }
}

// ---------------- Kernel 2: fused scores + softmax -> split bf16 attn -------
// CTA = 32 query rows x FULL 1024-col row, K=64. grid (32 i-tiles, 32 bh).
__global__ __launch_bounds__(256) void scoresm() {
  __shared__ __nv_bfloat16 QH[32 * LDSTRIDE], QL[32 * LDSTRIDE];
  __shared__ __nv_bfloat16 KH[128 * LDSTRIDE], KL[128 * LDSTRIDE];
  __shared__ float red[32][4];

  int tid = threadIdx.x;
  int wid = tid >> 5, lane = tid & 31;
  int bh = blockIdx.y;
  int i0 = blockIdx.x * 32;

  const __nv_bfloat16* qh = g_qh + (size_t)bh * NSEQ * HD;
  const __nv_bfloat16* ql = g_ql + (size_t)bh * NSEQ * HD;
  const __nv_bfloat16* kh = g_kh + (size_t)bh * NSEQ * HD;
  const __nv_bfloat16* kl = g_kl + (size_t)bh * NSEQ * HD;

  {
    int r = tid >> 3, seg = tid & 7;
    int so = r * LDSTRIDE + seg * 8;
    *(uint4*)(QH + so) = *(const uint4*)(qh + (i0 + r) * 64 + seg * 8);
    *(uint4*)(QL + so) = *(const uint4*)(ql + (i0 + r) * 64 + seg * 8);
  }

  int mw = (wid & 1) * 16;
  int nwb = (wid >> 1) * 32;
  int r = lane >> 2, kq = (lane & 3) * 2;

  uint32_t ah[4][4], al[4][4];
  float acc[8][4][4];
#pragma unroll
  for (int jc = 0; jc < 8; jc++)
#pragma unroll
    for (int nt = 0; nt < 4; nt++)
#pragma unroll
      for (int e = 0; e < 4; e++) acc[jc][nt][e] = 0.f;

#pragma unroll
  for (int jc = 0; jc < 8; jc++) {
    if (jc) __syncthreads();
#pragma unroll
    for (int t = 0; t < 4; t++) {
      int idx = tid + 256 * t;
      int rr = idx >> 3, seg = idx & 7;
      int so = rr * LDSTRIDE + seg * 8;
      *(uint4*)(KH + so) = *(const uint4*)(kh + (jc * 128 + rr) * 64 + seg * 8);
      *(uint4*)(KL + so) = *(const uint4*)(kl + (jc * 128 + rr) * 64 + seg * 8);
    }
    __syncthreads();
    if (jc == 0) {
#pragma unroll
      for (int kb = 0; kb < 4; kb++) {
        const __nv_bfloat16* p = QH + (mw + r) * LDSTRIDE + kb * 16 + kq;
        ah[kb][0] = *(const uint32_t*)p;
        ah[kb][1] = *(const uint32_t*)(p + 8 * LDSTRIDE);
        ah[kb][2] = *(const uint32_t*)(p + 8);
        ah[kb][3] = *(const uint32_t*)(p + 8 * LDSTRIDE + 8);
        const __nv_bfloat16* q = QL + (mw + r) * LDSTRIDE + kb * 16 + kq;
        al[kb][0] = *(const uint32_t*)q;
        al[kb][1] = *(const uint32_t*)(q + 8 * LDSTRIDE);
        al[kb][2] = *(const uint32_t*)(q + 8);
        al[kb][3] = *(const uint32_t*)(q + 8 * LDSTRIDE + 8);
      }
    }
#pragma unroll
    for (int kb = 0; kb < 4; kb++) {
#pragma unroll
      for (int nt = 0; nt < 4; nt++) {
        int nrow = nwb + nt * 8 + r;
        const __nv_bfloat16* p = KH + nrow * LDSTRIDE + kb * 16 + kq;
        uint32_t bhf[2] = {*(const uint32_t*)p, *(const uint32_t*)(p + 8)};
        const __nv_bfloat16* q = KL + nrow * LDSTRIDE + kb * 16 + kq;
        uint32_t blf[2] = {*(const uint32_t*)q, *(const uint32_t*)(q + 8)};
        mma16816(acc[jc][nt], ah[kb], bhf);
        mma16816(acc[jc][nt], ah[kb], blf);
        mma16816(acc[jc][nt], al[kb], bhf);
      }
    }
  }

  int r0 = mw + r, r1 = r0 + 8;
  float m0 = -1e30f, m1 = -1e30f;
#pragma unroll
  for (int jc = 0; jc < 8; jc++)
#pragma unroll
    for (int nt = 0; nt < 4; nt++) {
      m0 = fmaxf(m0, fmaxf(acc[jc][nt][0], acc[jc][nt][1]));
      m1 = fmaxf(m1, fmaxf(acc[jc][nt][2], acc[jc][nt][3]));
    }
#pragma unroll
  for (int o = 1; o <= 2; o <<= 1) {
    m0 = fmaxf(m0, __shfl_xor_sync(~0u, m0, o));
    m1 = fmaxf(m1, __shfl_xor_sync(~0u, m1, o));
  }
  if ((lane & 3) == 0) { red[r0][wid >> 1] = m0; red[r1][wid >> 1] = m1; }
  __syncthreads();
  m0 = fmaxf(fmaxf(red[r0][0], red[r0][1]), fmaxf(red[r0][2], red[r0][3]));
  m1 = fmaxf(fmaxf(red[r1][0], red[r1][1]), fmaxf(red[r1][2], red[r1][3]));
  __syncthreads();

  float s0 = 0.f, s1 = 0.f;
#pragma unroll
  for (int jc = 0; jc < 8; jc++)
#pragma unroll
    for (int nt = 0; nt < 4; nt++) {
      acc[jc][nt][0] = __expf(acc[jc][nt][0] - m0);
      acc[jc][nt][1] = __expf(acc[jc][nt][1] - m0);
      acc[jc][nt][2] = __expf(acc[jc][nt][2] - m1);
      acc[jc][nt][3] = __expf(acc[jc][nt][3] - m1);
      s0 += acc[jc][nt][0] + acc[jc][nt][1];
      s1 += acc[jc][nt][2] + acc[jc][nt][3];
    }
#pragma unroll
  for (int o = 1; o <= 2; o <<= 1) {
    s0 += __shfl_xor_sync(~0u, s0, o);
    s1 += __shfl_xor_sync(~0u, s1, o);
  }
  if ((lane & 3) == 0) { red[r0][wid >> 1] = s0; red[r1][wid >> 1] = s1; }
  __syncthreads();
  s0 = red[r0][0] + red[r0][1] + red[r0][2] + red[r0][3];
  s1 = red[r1][0] + red[r1][1] + red[r1][2] + red[r1][3];
  float inv0 = 1.f / s0, inv1 = 1.f / s1;

  size_t base0 = (((size_t)bh << 10) + (i0 + r0)) << 10;
  size_t base1 = (((size_t)bh << 10) + (i0 + r1)) << 10;
#pragma unroll
  for (int jc = 0; jc < 8; jc++) {
#pragma unroll
    for (int nt = 0; nt < 4; nt++) {
      int col = jc * 128 + nwb + nt * 8 + (lane & 3) * 2;
      float e0 = acc[jc][nt][0] * inv0, e1 = acc[jc][nt][1] * inv0;
      float e2 = acc[jc][nt][2] * inv1, e3 = acc[jc][nt][3] * inv1;
      B16x2 hp, lp;
      split2(e0, hp.h[0], lp.h[0]); split2(e1, hp.h[1], lp.h[1]);
      *(uint32_t*)(g_attn_h + base0 + col) = hp.u;
      *(uint32_t*)(g_attn_l + base0 + col) = lp.u;
      split2(e2, hp.h[0], lp.h[0]); split2(e3, hp.h[1], lp.h[1]);
      *(uint32_t*)(g_attn_h + base1 + col) = hp.u;
      *(uint32_t*)(g_attn_l + base1 + col) = lp.u;
    }
  }
}

// ---------------- Kernel 3: out_head = attn @ v via mma.sync ----------------
__global__ __launch_bounds__(256) void av_mma() {
  extern __shared__ __nv_bfloat16 sm[];
  __nv_bfloat16* AHs = sm;
  __nv_bfloat16* ALs = AHs + 128 * LDSTRIDE;
  __nv_bfloat16* VHs = ALs + 128 * LDSTRIDE;
  __nv_bfloat16* VLs = VHs + 64 * LDSTRIDE;

  int tid = threadIdx.x;
  int wid = tid >> 5, lane = tid & 31;
  int bh = blockIdx.y;
  int i0 = blockIdx.x * 128;

  const __nv_bfloat16* vth = g_vth + (size_t)bh * HD * NSEQ;
  const __nv_bfloat16* vtl = g_vtl + (size_t)bh * HD * NSEQ;

  int m_w = (wid >> 1) * 32;
  int n_w = (wid & 1) * 32;
  int r = lane >> 2, kq = (lane & 3) * 2;

  float c[2][4][4];
#pragma unroll
  for (int mt = 0; mt < 2; mt++)
#pragma unroll
    for (int nt = 0; nt < 4; nt++)
#pragma unroll
      for (int e = 0; e < 4; e++) c[mt][nt][e] = 0.f;

  for (int ck = 0; ck < 16; ck++) {
    __syncthreads();
#pragma unroll
    for (int t = 0; t < 4; t++) {
      int idx = tid + 256 * t;
      int rr = idx >> 3, seg = idx & 7;
      size_t gsrc = ((((size_t)bh << 10) + i0 + rr) << 10) + ck * 64 + seg * 8;
      int so = rr * LDSTRIDE + seg * 8;
      *(uint4*)(AHs + so) = *(const uint4*)(g_attn_h + gsrc);
      *(uint4*)(ALs + so) = *(const uint4*)(g_attn_l + gsrc);
    }
#pragma unroll
    for (int t = 0; t < 2; t++) {
      int idx = tid + 256 * t;
      int d = idx >> 3, seg = idx & 7;
      int so = d * LDSTRIDE + seg * 8;
      *(uint4*)(VHs + so) =
          *(const uint4*)(vth + (size_t)d * 1024 + ck * 64 + seg * 8);
      *(uint4*)(VLs + so) =
          *(const uint4*)(vtl + (size_t)d * 1024 + ck * 64 + seg * 8);
    }
    __syncthreads();

#pragma unroll
    for (int kb = 0; kb < 64; kb += 16) {
      uint32_t ah[2][4], al[2][4];
#pragma unroll
      for (int mt = 0; mt < 2; mt++) {
        int row = m_w + mt * 16 + r;
        const __nv_bfloat16* p = AHs + row * LDSTRIDE + kb + kq;
        ah[mt][0] = *(const uint32_t*)p;
        ah[mt][1] = *(const uint32_t*)(p + 8 * LDSTRIDE);
        ah[mt][2] = *(const uint32_t*)(p + 8);
        ah[mt][3] = *(const uint32_t*)(p + 8 * LDSTRIDE + 8);
        const __nv_bfloat16* q = ALs + row * LDSTRIDE + kb + kq;
        al[mt][0] = *(const uint32_t*)q;
        al[mt][1] = *(const uint32_t*)(q + 8 * LDSTRIDE);
        al[mt][2] = *(const uint32_t*)(q + 8);
        al[mt][3] = *(const uint32_t*)(q + 8 * LDSTRIDE + 8);
      }
      uint32_t bhf[4][2], blf[4][2];
#pragma unroll
      for (int nt = 0; nt < 4; nt++) {
        int nrow = n_w + nt * 8 + r;
        const __nv_bfloat16* p = VHs + nrow * LDSTRIDE + kb + kq;
        bhf[nt][0] = *(const uint32_t*)p;
        bhf[nt][1] = *(const uint32_t*)(p + 8);
        const __nv_bfloat16* q = VLs + nrow * LDSTRIDE + kb + kq;
        blf[nt][0] = *(const uint32_t*)q;
        blf[nt][1] = *(const uint32_t*)(q + 8);
      }
#pragma unroll
      for (int mt = 0; mt < 2; mt++)
#pragma unroll
        for (int nt = 0; nt < 4; nt++) {
          mma16816(c[mt][nt], ah[mt], bhf[nt]);
          mma16816(c[mt][nt], ah[mt], blf[nt]);
          mma16816(c[mt][nt], al[mt], bhf[nt]);
        }
    }
  }

#pragma unroll
  for (int mt = 0; mt < 2; mt++) {
#pragma unroll
    for (int nt = 0; nt < 4; nt++) {
      int row = i0 + m_w + mt * 16 + r;
      int col = n_w + nt * 8 + (lane & 3) * 2;
      float* dst = g_oh + ((size_t)bh * 1024 + row) * 64 + col;
      *(float2*)dst = make_float2(c[mt][nt][0], c[mt][nt][1]);
      *(float2*)(dst + 8 * 64) = make_float2(c[mt][nt][2], c[mt][nt][3]);
    }
  }
}

// ---------------- Kernel 4: pe_sum via mma (pe hi only, 2-pass) -------------
__global__ __launch_bounds__(256) void pes_mma(const float* __restrict__ pe) {
  __shared__ __nv_bfloat16 AH[32 * PSTRIDE], AL[32 * PSTRIDE];
  __shared__ __nv_bfloat16 PH[32 * PSTRIDE];

  int tid = threadIdx.x;
  int wid = tid >> 5, lane = tid & 31;
  int i = blockIdx.x;
  int mw = (wid & 1) * 16;        // bh rows
  int nw = (wid >> 1) * 8;        // c cols
  int r = lane >> 2, kq = (lane & 3) * 2;

  float acc[4] = {};
  for (int kc = 0; kc < 8; kc++) {
    if (kc) __syncthreads();
#pragma unroll
    for (int t = 0; t < 2; t++) {
      int idx = tid + 256 * t;
      int row = idx >> 4, seg = idx & 15;
      size_t gsrc = ((size_t)row << 20) + ((size_t)i << 10) + kc * 128 + seg * 8;
      int so = row * PSTRIDE + seg * 8;
      *(uint4*)(AH + so) = *(const uint4*)(g_attn_h + gsrc);
      *(uint4*)(AL + so) = *(const uint4*)(g_attn_l + gsrc);
    }
    // stage pe[i] chunk transposed (hi only): peT[c][j]
#pragma unroll
    for (int t = 0; t < 4; t++) {
      int idx = tid + 256 * t;
      int j = idx >> 3, c4 = idx & 7;
      float4 v = *(const float4*)(
          pe + (((size_t)i << 10) + kc * 128 + j) * 32 + c4 * 4);
      PH[(c4 * 4 + 0) * PSTRIDE + j] = __float2bfloat16_rn(v.x);
      PH[(c4 * 4 + 1) * PSTRIDE + j] = __float2bfloat16_rn(v.y);
      PH[(c4 * 4 + 2) * PSTRIDE + j] = __float2bfloat16_rn(v.z);
      PH[(c4 * 4 + 3) * PSTRIDE + j] = __float2bfloat16_rn(v.w);
    }
    __syncthreads();
#pragma unroll
    for (int kb = 0; kb < 8; kb++) {
      const __nv_bfloat16* p = AH + (mw + r) * PSTRIDE + kb * 16 + kq;
      uint32_t ah4[4] = {*(const uint32_t*)p,
                         *(const uint32_t*)(p + 8 * PSTRIDE),
                         *(const uint32_t*)(p + 8),
                         *(const uint32_t*)(p + 8 * PSTRIDE + 8)};
      const __nv_bfloat16* q = AL + (mw + r) * PSTRIDE + kb * 16 + kq;
      uint32_t al4[4] = {*(const uint32_t*)q,
                         *(const uint32_t*)(q + 8 * PSTRIDE),
                         *(const uint32_t*)(q + 8),
                         *(const uint32_t*)(q + 8 * PSTRIDE + 8)};
      const __nv_bfloat16* pb = PH + (nw + r) * PSTRIDE + kb * 16 + kq;
      uint32_t bh2[2] = {*(const uint32_t*)pb, *(const uint32_t*)(pb + 8)};
      mma16816(acc, ah4, bh2);
      mma16816(acc, al4, bh2);
    }
  }
  int c = nw + (lane & 3) * 2;
  int b0 = mw + r, b1 = b0 + 8;
  *(float2*)&g_pes[(((size_t)b0 << 10) + i) * 32 + c] = make_float2(acc[0], acc[1]);
  *(float2*)&g_pes[(((size_t)b1 << 10) + i) * 32 + c] = make_float2(acc[2], acc[3]);
}

// ---------------- Kernel 5: merged = out_head + pe_sum@Wpe + bpe (split) ----
__global__ __launch_bounds__(256) void merge_kernel(
    const float* __restrict__ Wpe, const float* __restrict__ bpe) {
  __shared__ float wpe_s[32 * 64];
  __shared__ float pes_s[32 * 32];
  __shared__ float bpe_s[64];
  int bh = blockIdx.x;
  int n0 = blockIdx.y * 32;
  int tid = threadIdx.x;
#pragma unroll
  for (int r = 0; r < 8; r++) wpe_s[tid + r * 256] = Wpe[tid + r * 256];
  if (tid < 64) bpe_s[tid] = bpe[tid];
  {
    int nl = tid >> 3, cc = tid & 7;
    *(float4*)&pes_s[nl * 32 + cc * 4] =
        *(const float4*)(g_pes + ((size_t)bh * 1024 + n0 + nl) * 32 + cc * 4);
  }
  __syncthreads();
  int nl = tid >> 3;
  int d0 = (tid & 7) * 8;
  int b = bh >> 3, h = bh & 7;
  const float* ohp = g_oh + ((size_t)bh * 1024 + n0 + nl) * 64 + d0;
  float o[8];
#pragma unroll
  for (int dd = 0; dd < 8; dd++) o[dd] = bpe_s[d0 + dd] + ohp[dd];
#pragma unroll 8
  for (int c = 0; c < 32; c++) {
    float pv = pes_s[nl * 32 + c];
#pragma unroll
    for (int dd = 0; dd < 8; dd++) o[dd] += pv * wpe_s[c * 64 + d0 + dd];
  }
  size_t mp = ((size_t)(b * 1024 + n0 + nl)) * 512 + h * 64 + d0;
  B16x8 hh, ll;
#pragma unroll
  for (int dd = 0; dd < 8; dd++) split2(o[dd], hh.h[dd], ll.h[dd]);
  *(uint4*)&g_mh[mp] = hh.u;
  *(uint4*)&g_ml[mp] = ll.u;
}

// ---------------- Kernel 6: out = merged @ Wproj via mma.sync ----------------
// M=4096, N=256, K=512. CTA 128m x 64n, grid (32, 4).
__global__ __launch_bounds__(256) void proj_mma(float* __restrict__ out) {
  extern __shared__ __nv_bfloat16 sm[];
  __nv_bfloat16* MH = sm;
  __nv_bfloat16* ML = MH + 128 * LDSTRIDE;
  __nv_bfloat16* WH = ML + 128 * LDSTRIDE;
  __nv_bfloat16* WL = WH + 64 * LDSTRIDE;

  int tid = threadIdx.x;
  int wid = tid >> 5, lane = tid & 31;
  int m0 = blockIdx.x * 128;
  int n0 = blockIdx.y * 64;

  int m_w = (wid >> 1) * 32, n_w = (wid & 1) * 32;
  int r = lane >> 2, kq = (lane & 3) * 2;

  float c[2][4][4];
#pragma unroll
  for (int mt = 0; mt < 2; mt++)
#pragma unroll
    for (int nt = 0; nt < 4; nt++)
#pragma unroll
      for (int e = 0; e < 4; e++) c[mt][nt][e] = 0.f;

  for (int ck = 0; ck < 8; ck++) {
    if (ck) __syncthreads();
#pragma unroll
    for (int t = 0; t < 4; t++) {
      int idx = tid + 256 * t;
      int rr = idx >> 3, seg = idx & 7;
      int so = rr * LDSTRIDE + seg * 8;
      size_t gs = (size_t)(m0 + rr) * 512 + ck * 64 + seg * 8;
      *(uint4*)(MH + so) = *(const uint4*)(g_mh + gs);
      *(uint4*)(ML + so) = *(const uint4*)(g_ml + gs);
    }
#pragma unroll
    for (int t = 0; t < 2; t++) {
      int idx = tid + 256 * t;
      int d = idx >> 3, seg = idx & 7;
      int so = d * LDSTRIDE + seg * 8;
      size_t gs = (size_t)(n0 + d) * 512 + ck * 64 + seg * 8;
      *(uint4*)(WH + so) = *(const uint4*)(g_wpth + gs);
      *(uint4*)(WL + so) = *(const uint4*)(g_wptl + gs);
    }
    __syncthreads();
#pragma unroll
    for (int kb = 0; kb < 64; kb += 16) {
      uint32_t ah[2][4], al[2][4];
#pragma unroll
      for (int mt = 0; mt < 2; mt++) {
        int row = m_w + mt * 16 + r;
        const __nv_bfloat16* p = MH + row * LDSTRIDE + kb + kq;
        ah[mt][0] = *(const uint32_t*)p;
        ah[mt][1] = *(const uint32_t*)(p + 8 * LDSTRIDE);
        ah[mt][2] = *(const uint32_t*)(p + 8);
        ah[mt][3] = *(const uint32_t*)(p + 8 * LDSTRIDE + 8);
        const __nv_bfloat16* q = ML + row * LDSTRIDE + kb + kq;
        al[mt][0] = *(const uint32_t*)q;
        al[mt][1] = *(const uint32_t*)(q + 8 * LDSTRIDE);
        al[mt][2] = *(const uint32_t*)(q + 8);
        al[mt][3] = *(const uint32_t*)(q + 8 * LDSTRIDE + 8);
      }
      uint32_t bhf[4][2], blf[4][2];
#pragma unroll
      for (int nt = 0; nt < 4; nt++) {
        int nrow = n_w + nt * 8 + r;
        const __nv_bfloat16* p = WH + nrow * LDSTRIDE + kb + kq;
        bhf[nt][0] = *(const uint32_t*)p;
        bhf[nt][1] = *(const uint32_t*)(p + 8);
        const __nv_bfloat16* q = WL + nrow * LDSTRIDE + kb + kq;
        blf[nt][0] = *(const uint32_t*)q;
        blf[nt][1] = *(const uint32_t*)(q + 8);
      }
#pragma unroll
      for (int mt = 0; mt < 2; mt++)
#pragma unroll
        for (int nt = 0; nt < 4; nt++) {
          mma16816(c[mt][nt], ah[mt], bhf[nt]);
          mma16816(c[mt][nt], ah[mt], blf[nt]);
          mma16816(c[mt][nt], al[mt], bhf[nt]);
        }
    }
  }

#pragma unroll
  for (int mt = 0; mt < 2; mt++) {
#pragma unroll
    for (int nt = 0; nt < 4; nt++) {
      int row = m0 + m_w + mt * 16 + r;
      int col = n0 + n_w + nt * 8 + (lane & 3) * 2;
      float* dst = out + (size_t)row * 256 + col;
      *(float2*)dst = make_float2(c[mt][nt][0], c[mt][nt][1]);
      *(float2*)(dst + 8 * 256) = make_float2(c[mt][nt][2], c[mt][nt][3]);
    }
  }
}

// ---------------- launch -----------------------------------------------------
extern "C" void kernel_launch(void* const* d_in, const int* in_sizes, int n_in,
                              void* d_out, int out_size) {
  const float* x     = (const float*)d_in[0];
  const float* pe    = (const float*)d_in[1];
  const float* Wq    = (const float*)d_in[2];
  const float* Wk    = (const float*)d_in[3];
  const float* Wv    = (const float*)d_in[4];
  const float* bv    = (const float*)d_in[5];
  const float* Wpe   = (const float*)d_in[6];
  const float* bpe   = (const float*)d_in[7];
  const float* Wproj = (const float*)d_in[8];
  float* out = (float*)d_out;

  cudaFuncSetAttribute(qkv_mma, cudaFuncAttributeMaxDynamicSharedMemorySize,
                       GEMM_SMEM_BYTES);
  cudaFuncSetAttribute(av_mma, cudaFuncAttributeMaxDynamicSharedMemorySize,
                       GEMM_SMEM_BYTES);
  cudaFuncSetAttribute(proj_mma, cudaFuncAttributeMaxDynamicSharedMemorySize,
                       GEMM_SMEM_BYTES);

  split_x<<<1024, 256>>>(x);
  prep_w<<<512, 256>>>(Wq, Wk, Wv, Wproj);
  qkv_mma<<<dim3(32, 24), 256, GEMM_SMEM_BYTES>>>(bv);
  scoresm<<<dim3(32, 32), 256>>>();
  av_mma<<<dim3(8, 32), 256, GEMM_SMEM_BYTES>>>();
  pes_mma<<<1024, 256>>>(pe);
  merge_kernel<<<dim3(32, 32), 256>>>(Wpe, bpe);
  proj_mma<<<dim3(32, 4), 256, GEMM_SMEM_BYTES>>>(out);
}